// round 9
// baseline (speedup 1.0000x reference)
#include <cuda_runtime.h>
#include <cuda_fp16.h>
#include <cstdint>

#define T_STEPS 256
#define BATCH   64
#define XDIM    512
#define HDIM    2048
#define G4      8192
#define NCTAS   128
#define PTHREADS 512
#define XTHREADS 256
#define KT      64                 // K-tile per stage (halfs) = 128 B rows
#define TILEHALFS (64*KT)
#define STAGES  4                  // xproj stages
#define PSTAGES 6                  // persistent-kernel stages
#define ASTG    8192               // stage tile bytes (64 rows * 128 B)
#define GSTR    68                 // gsum row stride (halfs)
#define GSLAB   (64*GSTR)          // halfs per slab

// persistent smem layout (bytes)
#define OFF_SB   (2*PSTAGES*ASTG)            // 98304  (A: 2 groups * 6 stages)
#define OFF_GSUM (OFF_SB + 2*PSTAGES*ASTG)   // 196608 (B same size)
#define PSMEM    (OFF_GSUM + 4*GSLAB*2)      // + 4 fp16 slabs = 231424 B

// ---------------- device scratch ----------------
__device__ __align__(16) __half d_in16 [T_STEPS * BATCH * XDIM];
__device__ __align__(16) __half d_wih16[G4 * XDIM];
__device__ __align__(16) __half d_whh16[G4 * HDIM];
__device__ __align__(16) float  d_bsum [G4];
__device__ __align__(16) __half d_xproj[(size_t)T_STEPS * BATCH * G4];  // fp16 now
__device__ __align__(16) __half d_h16  [2][BATCH * HDIM];
__device__ __align__(16) float  d_sum  [T_STEPS * BATCH];
__device__ unsigned d_bar;

// ---------------- helpers ----------------
__device__ __forceinline__ void mma16816(float* c,
    uint32_t a0, uint32_t a1, uint32_t a2, uint32_t a3,
    uint32_t b0, uint32_t b1)
{
    asm volatile(
        "mma.sync.aligned.m16n8k16.row.col.f32.f16.f16.f32 "
        "{%0,%1,%2,%3},{%4,%5,%6,%7},{%8,%9},{%0,%1,%2,%3};\n"
        : "+f"(c[0]), "+f"(c[1]), "+f"(c[2]), "+f"(c[3])
        : "r"(a0), "r"(a1), "r"(a2), "r"(a3), "r"(b0), "r"(b1));
}
#define LDSM4(r0, r1, r2, r3, addr) \
    asm volatile("ldmatrix.sync.aligned.m8n8.x4.shared.b16 {%0,%1,%2,%3}, [%4];" \
        : "=r"(r0), "=r"(r1), "=r"(r2), "=r"(r3) : "r"(addr))

__device__ __forceinline__ float tanh_hw(float x) {
    float y;
    asm("tanh.approx.f32 %0, %1;" : "=f"(y) : "f"(x));
    return y;
}
__device__ __forceinline__ float sigmoid_hw(float x) {
    return fmaf(tanh_hw(0.5f * x), 0.5f, 0.5f);
}
__device__ __forceinline__ float exp_hw(float x) {
    float y;
    asm("ex2.approx.ftz.f32 %0, %1;" : "=f"(y) : "f"(x * 1.4426950408889634f));
    return y;
}

__device__ __forceinline__ uint32_t smem_u32(const void* p) {
    return (uint32_t)__cvta_generic_to_shared(p);
}
__device__ __forceinline__ int fperm(int r) { return ((r & 1) << 2) | ((r & 7) >> 1); }

#define CP16(dst_u32, src_ptr) \
    asm volatile("cp.async.cg.shared.global [%0], [%1], 16;\n" :: "r"(dst_u32), "l"(src_ptr))
#define CP_COMMIT() asm volatile("cp.async.commit_group;\n" ::: "memory")
#define CP_WAIT2()  asm volatile("cp.async.wait_group 2;\n" ::: "memory")
#define CP_WAIT4()  asm volatile("cp.async.wait_group 4;\n" ::: "memory")

// row permutation: dst row (CTA-major: cta*64 + gate*16 + jj) -> src gate row
__device__ __forceinline__ int perm_src_row(int r) {
    int cta = r >> 6;
    int ln  = r & 63;
    int gate = ln >> 4;
    int jj   = ln & 15;
    return gate * HDIM + cta * 16 + jj;
}

// ---------------- phase 0 ----------------
__global__ __launch_bounds__(256) void prep_kernel(
    const float* __restrict__ input, const float* __restrict__ h0,
    const float* __restrict__ c0,    const float* __restrict__ wih,
    const float* __restrict__ whh,   const float* __restrict__ bih,
    const float* __restrict__ bhh)
{
    (void)c0;
    const int i0 = blockIdx.x * blockDim.x + threadIdx.x;
    const int stride = gridDim.x * blockDim.x;
    if (i0 == 0) d_bar = 0u;
    for (int i = i0; i < T_STEPS * BATCH * XDIM; i += stride)
        d_in16[i] = __float2half(input[i]);
    for (int i = i0; i < G4 * XDIM; i += stride) {
        int r = i >> 9, k = i & (XDIM - 1);
        d_wih16[i] = __float2half(wih[perm_src_row(r) * XDIM + k]);
    }
    for (int i = i0; i < G4 * HDIM; i += stride) {
        int r = i >> 11, k = i & (HDIM - 1);
        d_whh16[i] = __float2half(whh[(size_t)perm_src_row(r) * HDIM + k]);
    }
    for (int i = i0; i < G4; i += stride) {
        int s = perm_src_row(i);
        d_bsum[i] = bih[s] + bhh[s];
    }
    for (int i = i0; i < BATCH * HDIM; i += stride)
        d_h16[0][i] = __float2half(h0[i]);
    for (int i = i0; i < T_STEPS * BATCH; i += stride)
        d_sum[i] = 0.0f;
}

// ---------------- phase 1: xproj (fp16 output) ----------------
__global__ __launch_bounds__(XTHREADS) void xproj_kernel()
{
    extern __shared__ __align__(16) char xsmem_raw[];
    __half* sAll = (__half*)xsmem_raw;
    __half* sA = sAll;
    __half* sB = sAll + STAGES * TILEHALFS;

    const int tid  = threadIdx.x;
    const int lane = tid & 31, wid = tid >> 5;
    const int wm = wid >> 1, wn = wid & 1;
    const int gq = lane >> 2, tq = lane & 3;
    const int fp = fperm(gq);
    const int n0 = blockIdx.x * 64;
    const int m0 = blockIdx.y * 64;

    const int lrow = tid >> 2, lch = tid & 3;
    const int fp_s = fperm(lrow);
    const uint32_t sAu = smem_u32(sA), sBu = smem_u32(sB);
    const uint32_t d0 = (uint32_t)(lrow * KT + ((lch ^ fp_s) * 8)) * 2;
    const uint32_t d1 = (uint32_t)(lrow * KT + (((lch + 4) ^ fp_s) * 8)) * 2;
    const int scol = lch * 8;

    const __half* Ag = d_in16  + (size_t)(m0 + lrow) * XDIM + scol;
    const __half* Bg = d_wih16 + (size_t)(n0 + lrow) * XDIM + scol;

    float acc[4][4];
    #pragma unroll
    for (int i = 0; i < 4; i++)
        #pragma unroll
        for (int j = 0; j < 4; j++) acc[i][j] = 0.0f;

    const int NITX = XDIM / KT;
    #pragma unroll
    for (int st = 0; st < 3; ++st) {
        const int kb = st * KT;
        CP16(sAu + (uint32_t)st * TILEHALFS * 2 + d0, Ag + kb);
        CP16(sAu + (uint32_t)st * TILEHALFS * 2 + d1, Ag + kb + 32);
        CP16(sBu + (uint32_t)st * TILEHALFS * 2 + d0, Bg + kb);
        CP16(sBu + (uint32_t)st * TILEHALFS * 2 + d1, Bg + kb + 32);
        CP_COMMIT();
    }

    const int rowA = wm * 16 + gq;
    #pragma unroll 1
    for (int it = 0; it < NITX; ++it) {
        CP_WAIT2();
        __syncthreads();
        const __half* At = sA + (it & 3) * TILEHALFS;
        const __half* Bt = sB + (it & 3) * TILEHALFS;
        #pragma unroll
        for (int k = 0; k < 4; ++k) {
            const int c0o = ((2 * k) ^ fp) * 8 + tq * 2;
            const int c1o = ((2 * k + 1) ^ fp) * 8 + tq * 2;
            uint32_t a0 = *(const uint32_t*)(At + rowA * KT + c0o);
            uint32_t a1 = *(const uint32_t*)(At + (rowA + 8) * KT + c0o);
            uint32_t a2 = *(const uint32_t*)(At + rowA * KT + c1o);
            uint32_t a3 = *(const uint32_t*)(At + (rowA + 8) * KT + c1o);
            #pragma unroll
            for (int nf = 0; nf < 4; nf++) {
                const int rowB = wn * 32 + nf * 8 + gq;
                uint32_t b0 = *(const uint32_t*)(Bt + rowB * KT + c0o);
                uint32_t b1 = *(const uint32_t*)(Bt + rowB * KT + c1o);
                mma16816(acc[nf], a0, a1, a2, a3, b0, b1);
            }
        }
        __syncthreads();
        const int nxt = it + 3;
        if (nxt < NITX) {
            const uint32_t so = (uint32_t)(nxt & 3) * TILEHALFS * 2;
            const int kb = nxt * KT;
            CP16(sAu + so + d0, Ag + kb);
            CP16(sAu + so + d1, Ag + kb + 32);
            CP16(sBu + so + d0, Bg + kb);
            CP16(sBu + so + d1, Bg + kb + 32);
        }
        CP_COMMIT();
    }

    #pragma unroll
    for (int nf = 0; nf < 4; nf++) {
        const int cb = n0 + wn * 32 + nf * 8 + tq * 2;
        const int r0 = m0 + wm * 16 + gq;
        float2 bsv = *(const float2*)(d_bsum + cb);
        __half2 v0 = __floats2half2_rn(acc[nf][0] + bsv.x, acc[nf][1] + bsv.y);
        __half2 v1 = __floats2half2_rn(acc[nf][2] + bsv.x, acc[nf][3] + bsv.y);
        *(__half2*)(d_xproj + (size_t)r0 * G4 + cb)       = v0;
        *(__half2*)(d_xproj + (size_t)(r0 + 8) * G4 + cb) = v1;
    }
}

// ---------------- grid barrier (128 CTAs co-resident) ----------------
__device__ __forceinline__ void grid_barrier(unsigned target)
{
    __syncthreads();
    if (threadIdx.x == 0) {
        __threadfence();
        atomicAdd(&d_bar, 1u);
        volatile unsigned* p = &d_bar;
        while (*p < target) { }
        __threadfence();
    }
    __syncthreads();
}

// ---------------- phase 2: persistent recurrent kernel ----------------
__global__ __launch_bounds__(PTHREADS, 1) void lstm_persistent_c0(
    float* __restrict__ out, const float* __restrict__ c0)
{
    extern __shared__ __align__(1024) char smem_raw[];
    const uint32_t sbase = smem_u32(smem_raw);
    __half* gsum = (__half*)(smem_raw + OFF_GSUM);

    const int cta  = blockIdx.x;
    const int tid  = threadIdx.x;
    const int lane = tid & 31;
    const int g    = tid >> 8;              // K-half group (0,1)
    const int gtid = tid & 255;
    const int gwid = gtid >> 5;             // warp in group 0..7
    const int wm = gwid & 1;                // m half (batch 32)
    const int wn = (gwid >> 1) & 1;         // n half (gate 32)
    const int wk = gwid >> 2;               // k quarter within group
    const int gq = lane >> 2, tq = lane & 3;
    const int n0 = cta * 64;                // permuted gate-row base
    const int KOFF = g * (HDIM / 2);
    const int NIT  = (HDIM / 2) / KT;       // 16

    const uint32_t aGrp = sbase + (uint32_t)g * PSTAGES * ASTG;
    const uint32_t bGrp = sbase + OFF_SB + (uint32_t)g * PSTAGES * ASTG;

    const int lrow = gtid >> 2, lch = gtid & 3;
    const int fp_s = fperm(lrow);
    const uint32_t d0 = (uint32_t)(lrow * 128 + ((lch ^ fp_s) << 4));
    const uint32_t d1 = (uint32_t)(lrow * 128 + (((lch + 4) ^ fp_s) << 4));
    const int scol = lch * 8;
    const __half* Bg = d_whh16 + (size_t)(n0 + lrow) * HDIM + KOFF + scol;

    const int fp_l = fperm(lane & 7);
    const uint32_t rowA0 = (uint32_t)((wm * 32 + (lane & 15)) * 128);
    const uint32_t rowA1 = rowA0 + 16 * 128;
    const uint32_t rowB0 = (uint32_t)((wn * 32 + ((lane >> 4) & 1) * 8 + (lane & 7)) * 128);
    const uint32_t rowB1 = rowB0 + 16 * 128;
    const int khA = (lane >> 4) & 1;
    const int khB = (lane >> 3) & 1;
    const int kb16 = wk * 2;

    const size_t HOFF = (size_t)T_STEPS * BATCH * HDIM;
    const size_t COFF = HOFF + (size_t)BATCH * HDIM;

    const int b1 = tid >> 4,        jj1 = tid & 15;
    const int b2 = 32 + (tid >> 4), jj2 = jj1;
    float creg1 = c0[b1 * HDIM + cta * 16 + jj1];
    float creg2 = c0[b2 * HDIM + cta * 16 + jj2];

    unsigned bar_target = 0;

#define ISSUE(SLOT, KB, HB) do {                                              \
        const __half* asrc_ = (HB) + (size_t)lrow * HDIM + KOFF + (KB) + scol;\
        const __half* bsrc_ = Bg + (KB);                                      \
        const uint32_t ao_ = aGrp + (uint32_t)(SLOT) * ASTG;                  \
        const uint32_t bo_ = bGrp + (uint32_t)(SLOT) * ASTG;                  \
        CP16(ao_ + d0, asrc_);                                                \
        CP16(ao_ + d1, asrc_ + 32);                                           \
        CP16(bo_ + d0, bsrc_);                                                \
        CP16(bo_ + d1, bsrc_ + 32);                                           \
        CP_COMMIT();                                                          \
    } while (0)

    // initial prologue: 5 stages of step 0
    {
        const __half* hbuf = d_h16[0];
        #pragma unroll
        for (int st = 0; st < 5; ++st) ISSUE(st, st * KT, hbuf);
    }

    #pragma unroll 1
    for (int t = 0; t < T_STEPS; ++t) {
        const __half* hbuf = d_h16[t & 1];

        // prefetch this step's xproj gate values (fp16, hidden behind GEMM)
        const __half* xp = d_xproj + (size_t)t * BATCH * G4 + n0;
        const __half* xr1 = xp + (size_t)b1 * G4;
        const __half* xr2 = xp + (size_t)b2 * G4;
        float xv1[4], xv2[4];
        #pragma unroll
        for (int q = 0; q < 4; ++q) {
            xv1[q] = __half2float(xr1[q * 16 + jj1]);
            xv2[q] = __half2float(xr2[q * 16 + jj2]);
        }

        float acc[2][4][4];
        #pragma unroll
        for (int i = 0; i < 2; i++)
            #pragma unroll
            for (int j = 0; j < 4; j++)
                #pragma unroll
                for (int q = 0; q < 4; q++) acc[i][j][q] = 0.0f;

        // cyclic slot counters (no runtime mod)
        int rd = 0;        // slot for iteration it
        int wr = 5;        // slot for stage it+5
        #pragma unroll 4
        for (int it = 0; it < NIT; ++it) {
            CP_WAIT4();
            asm volatile("bar.sync %0, 256;\n" :: "r"(g + 1) : "memory");
            const uint32_t At = aGrp + (uint32_t)rd * ASTG;
            const uint32_t Bt = bGrp + (uint32_t)rd * ASTG;
            #pragma unroll
            for (int kc = 0; kc < 2; ++kc) {
                const uint32_t ccA = (uint32_t)((((kb16 + kc) << 1) | khA) ^ fp_l) << 4;
                const uint32_t ccB = (uint32_t)((((kb16 + kc) << 1) | khB) ^ fp_l) << 4;
                uint32_t a0[4], a1[4], bb0[4], bb1[4];
                LDSM4(a0[0], a0[1], a0[2], a0[3], At + rowA0 + ccA);
                LDSM4(a1[0], a1[1], a1[2], a1[3], At + rowA1 + ccA);
                LDSM4(bb0[0], bb0[1], bb0[2], bb0[3], Bt + rowB0 + ccB);
                LDSM4(bb1[0], bb1[1], bb1[2], bb1[3], Bt + rowB1 + ccB);
                mma16816(acc[0][0], a0[0], a0[1], a0[2], a0[3], bb0[0], bb0[1]);
                mma16816(acc[0][1], a0[0], a0[1], a0[2], a0[3], bb0[2], bb0[3]);
                mma16816(acc[0][2], a0[0], a0[1], a0[2], a0[3], bb1[0], bb1[1]);
                mma16816(acc[0][3], a0[0], a0[1], a0[2], a0[3], bb1[2], bb1[3]);
                mma16816(acc[1][0], a1[0], a1[1], a1[2], a1[3], bb0[0], bb0[1]);
                mma16816(acc[1][1], a1[0], a1[1], a1[2], a1[3], bb0[2], bb0[3]);
                mma16816(acc[1][2], a1[0], a1[1], a1[2], a1[3], bb1[0], bb1[1]);
                mma16816(acc[1][3], a1[0], a1[1], a1[2], a1[3], bb1[2], bb1[3]);
            }
            const int nxt = it + 5;
            if (nxt < NIT) {
                ISSUE(wr, nxt * KT, hbuf);
            } else {
                CP_COMMIT();
            }
            rd = (rd == PSTAGES - 1) ? 0 : rd + 1;
            wr = (wr == PSTAGES - 1) ? 0 : wr + 1;
        }

        // epilogue: write this warp's partial slab in fp16 (slab = g*2 + wk)
        {
            __half* gs = gsum + (size_t)(g * 2 + wk) * GSLAB;
            #pragma unroll
            for (int mf = 0; mf < 2; ++mf) {
                const int row = wm * 32 + mf * 16 + gq;
                #pragma unroll
                for (int nf = 0; nf < 4; ++nf) {
                    const int col = wn * 32 + nf * 8 + tq * 2;
                    *(__half2*)&gs[row * GSTR + col] =
                        __floats2half2_rn(acc[mf][nf][0], acc[mf][nf][1]);
                    *(__half2*)&gs[(row + 8) * GSTR + col] =
                        __floats2half2_rn(acc[mf][nf][2], acc[mf][nf][3]);
                }
            }
        }
        __syncthreads();

        // pointwise LSTM + exp + partial softmax sum
        __half* hN = d_h16[(t + 1) & 1];
        float e1, e2;
        {
            const __half* gb = gsum + (size_t)b1 * GSTR;
            float ip = __half2float(gb[jj1]) + __half2float(gb[GSLAB + jj1])
                     + __half2float(gb[2*GSLAB + jj1]) + __half2float(gb[3*GSLAB + jj1]) + xv1[0];
            float fpv= __half2float(gb[16+jj1]) + __half2float(gb[GSLAB+16+jj1])
                     + __half2float(gb[2*GSLAB+16+jj1]) + __half2float(gb[3*GSLAB+16+jj1]) + xv1[1];
            float gp = __half2float(gb[32+jj1]) + __half2float(gb[GSLAB+32+jj1])
                     + __half2float(gb[2*GSLAB+32+jj1]) + __half2float(gb[3*GSLAB+32+jj1]) + xv1[2];
            float op = __half2float(gb[48+jj1]) + __half2float(gb[GSLAB+48+jj1])
                     + __half2float(gb[2*GSLAB+48+jj1]) + __half2float(gb[3*GSLAB+48+jj1]) + xv1[3];
            float ii = sigmoid_hw(ip), ff = sigmoid_hw(fpv);
            float gg = tanh_hw(gp),    oo = sigmoid_hw(op);
            float cn = ff * creg1 + ii * gg;
            creg1 = cn;
            float hn = oo * tanh_hw(cn);
            hN[b1 * HDIM + cta * 16 + jj1] = __float2half(hn);
            if (t == T_STEPS - 1) {
                out[HOFF + (size_t)b1 * HDIM + cta * 16 + jj1] = hn;
                out[COFF + (size_t)b1 * HDIM + cta * 16 + jj1] = cn;
            }
            e1 = exp_hw(hn);
        }
        {
            const __half* gb = gsum + (size_t)b2 * GSTR;
            float ip = __half2float(gb[jj2]) + __half2float(gb[GSLAB + jj2])
                     + __half2float(gb[2*GSLAB + jj2]) + __half2float(gb[3*GSLAB + jj2]) + xv2[0];
            float fpv= __half2float(gb[16+jj2]) + __half2float(gb[GSLAB+16+jj2])
                     + __half2float(gb[2*GSLAB+16+jj2]) + __half2float(gb[3*GSLAB+16+jj2]) + xv2[1];
            float gp = __half2float(gb[32+jj2]) + __half2float(gb[GSLAB+32+jj2])
                     + __half2float(gb[2*GSLAB+32+jj2]) + __half2float(gb[3*GSLAB+32+jj2]) + xv2[2];
            float op = __half2float(gb[48+jj2]) + __half2float(gb[GSLAB+48+jj2])
                     + __half2float(gb[2*GSLAB+48+jj2]) + __half2float(gb[3*GSLAB+48+jj2]) + xv2[3];
            float ii = sigmoid_hw(ip), ff = sigmoid_hw(fpv);
            float gg = tanh_hw(gp),    oo = sigmoid_hw(op);
            float cn = ff * creg2 + ii * gg;
            creg2 = cn;
            float hn = oo * tanh_hw(cn);
            hN[b2 * HDIM + cta * 16 + jj2] = __float2half(hn);
            if (t == T_STEPS - 1) {
                out[HOFF + (size_t)b2 * HDIM + cta * 16 + jj2] = hn;
                out[COFF + (size_t)b2 * HDIM + cta * 16 + jj2] = cn;
            }
            e2 = exp_hw(hn);
        }
        float v1 = e1, v2 = e2;
        #pragma unroll
        for (int o = 8; o > 0; o >>= 1) {
            v1 += __shfl_xor_sync(0xffffffffu, v1, o);
            v2 += __shfl_xor_sync(0xffffffffu, v2, o);
        }
        if ((lane & 15) == 0) {
            atomicAdd(&d_sum[t * BATCH + b1], v1);
            atomicAdd(&d_sum[t * BATCH + b2], v2);
        }

        bar_target += NCTAS;
        grid_barrier(bar_target);

        // d_sum loads first (overlap with prologue issuance), then prologue,
        // then normalize with the already-inflight loads
        float s1 = __ldcg(&d_sum[t * BATCH + b1]);
        float s2 = __ldcg(&d_sum[t * BATCH + b2]);
        if (t + 1 < T_STEPS) {
            const __half* hnext = d_h16[(t + 1) & 1];
            #pragma unroll
            for (int st = 0; st < 5; ++st) ISSUE(st, st * KT, hnext);
        }
        {
            out[(size_t)t * BATCH * HDIM + (size_t)b1 * HDIM + cta * 16 + jj1] = e1 * (1.0f / s1);
            out[(size_t)t * BATCH * HDIM + (size_t)b2 * HDIM + cta * 16 + jj2] = e2 * (1.0f / s2);
        }
    }
#undef ISSUE
}

// ---------------- entry ----------------
extern "C" void kernel_launch(void* const* d_in, const int* in_sizes, int n_in,
                              void* d_out, int out_size)
{
    (void)in_sizes; (void)n_in; (void)out_size;
    const float* input = (const float*)d_in[0];
    const float* h0    = (const float*)d_in[1];
    const float* c0    = (const float*)d_in[2];
    const float* wih   = (const float*)d_in[3];
    const float* whh   = (const float*)d_in[4];
    const float* bih   = (const float*)d_in[5];
    const float* bhh   = (const float*)d_in[6];

    const int xsmem = 2 * STAGES * TILEHALFS * (int)sizeof(__half);
    cudaFuncSetAttribute(xproj_kernel,
                         cudaFuncAttributeMaxDynamicSharedMemorySize, xsmem);
    cudaFuncSetAttribute(lstm_persistent_c0,
                         cudaFuncAttributeMaxDynamicSharedMemorySize, PSMEM);

    prep_kernel<<<1024, 256>>>(input, h0, c0, wih, whh, bih, bhh);
    xproj_kernel<<<dim3(G4 / 64, (T_STEPS * BATCH) / 64), XTHREADS, xsmem>>>();
    lstm_persistent_c0<<<NCTAS, PTHREADS, PSMEM>>>((float*)d_out, c0);
}

// round 10
// speedup vs baseline: 1.0476x; 1.0476x over previous
#include <cuda_runtime.h>
#include <cuda_fp16.h>
#include <cstdint>

#define T_STEPS 256
#define BATCH   64
#define XDIM    512
#define HDIM    2048
#define G4      8192
#define NCTAS   128
#define PTHREADS 512
#define XTHREADS 256
#define KT      64                 // K-tile per stage (halfs) = 128 B rows
#define TILEHALFS (64*KT)
#define STAGES  4                  // xproj stages
#define PSTAGES 6                  // persistent-kernel stages
#define ASTG    8192               // stage tile bytes (64 rows * 128 B)
#define GSTR    68                 // gsum row stride (halfs)
#define GSLAB   (64*GSTR)          // halfs per slab

// persistent smem layout (bytes)
#define OFF_SB   (2*PSTAGES*ASTG)            // 98304  (A: 2 groups * 6 stages)
#define OFF_GSUM (OFF_SB + 2*PSTAGES*ASTG)   // 196608 (B same size)
#define PSMEM    (OFF_GSUM + 4*GSLAB*2)      // + 4 fp16 slabs = 231424 B

// ---------------- device scratch ----------------
__device__ __align__(16) __half d_in16 [T_STEPS * BATCH * XDIM];
__device__ __align__(16) __half d_wih16[G4 * XDIM];
__device__ __align__(16) __half d_whh16[G4 * HDIM];
__device__ __align__(16) float  d_bsum [G4];
__device__ __align__(16) __half d_xproj[(size_t)T_STEPS * BATCH * G4];  // fp16
__device__ __align__(16) __half d_h16  [2][BATCH * HDIM];
__device__ __align__(16) float  d_sum  [T_STEPS * BATCH];
__device__ unsigned d_bar;

// ---------------- helpers ----------------
__device__ __forceinline__ void mma16816(float* c,
    uint32_t a0, uint32_t a1, uint32_t a2, uint32_t a3,
    uint32_t b0, uint32_t b1)
{
    asm volatile(
        "mma.sync.aligned.m16n8k16.row.col.f32.f16.f16.f32 "
        "{%0,%1,%2,%3},{%4,%5,%6,%7},{%8,%9},{%0,%1,%2,%3};\n"
        : "+f"(c[0]), "+f"(c[1]), "+f"(c[2]), "+f"(c[3])
        : "r"(a0), "r"(a1), "r"(a2), "r"(a3), "r"(b0), "r"(b1));
}
#define LDSM4(r0, r1, r2, r3, addr) \
    asm volatile("ldmatrix.sync.aligned.m8n8.x4.shared.b16 {%0,%1,%2,%3}, [%4];" \
        : "=r"(r0), "=r"(r1), "=r"(r2), "=r"(r3) : "r"(addr))

__device__ __forceinline__ float tanh_hw(float x) {
    float y;
    asm("tanh.approx.f32 %0, %1;" : "=f"(y) : "f"(x));
    return y;
}
__device__ __forceinline__ float sigmoid_hw(float x) {
    return fmaf(tanh_hw(0.5f * x), 0.5f, 0.5f);
}
__device__ __forceinline__ float exp_hw(float x) {
    float y;
    asm("ex2.approx.ftz.f32 %0, %1;" : "=f"(y) : "f"(x * 1.4426950408889634f));
    return y;
}

__device__ __forceinline__ uint32_t smem_u32(const void* p) {
    return (uint32_t)__cvta_generic_to_shared(p);
}
__device__ __forceinline__ int fperm(int r) { return ((r & 1) << 2) | ((r & 7) >> 1); }

#define CP16(dst_u32, src_ptr) \
    asm volatile("cp.async.cg.shared.global [%0], [%1], 16;\n" :: "r"(dst_u32), "l"(src_ptr))
#define CP_COMMIT() asm volatile("cp.async.commit_group;\n" ::: "memory")
#define CP_WAIT2()  asm volatile("cp.async.wait_group 2;\n" ::: "memory")
#define CP_WAIT4()  asm volatile("cp.async.wait_group 4;\n" ::: "memory")

// row permutation: dst row (CTA-major: cta*64 + gate*16 + jj) -> src gate row
__device__ __forceinline__ int perm_src_row(int r) {
    int cta = r >> 6;
    int ln  = r & 63;
    int gate = ln >> 4;
    int jj   = ln & 15;
    return gate * HDIM + cta * 16 + jj;
}

// ---------------- phase 0 ----------------
__global__ __launch_bounds__(256) void prep_kernel(
    const float* __restrict__ input, const float* __restrict__ h0,
    const float* __restrict__ c0,    const float* __restrict__ wih,
    const float* __restrict__ whh,   const float* __restrict__ bih,
    const float* __restrict__ bhh)
{
    (void)c0;
    const int i0 = blockIdx.x * blockDim.x + threadIdx.x;
    const int stride = gridDim.x * blockDim.x;
    if (i0 == 0) d_bar = 0u;
    for (int i = i0; i < T_STEPS * BATCH * XDIM; i += stride)
        d_in16[i] = __float2half(input[i]);
    for (int i = i0; i < G4 * XDIM; i += stride) {
        int r = i >> 9, k = i & (XDIM - 1);
        d_wih16[i] = __float2half(wih[perm_src_row(r) * XDIM + k]);
    }
    for (int i = i0; i < G4 * HDIM; i += stride) {
        int r = i >> 11, k = i & (HDIM - 1);
        d_whh16[i] = __float2half(whh[(size_t)perm_src_row(r) * HDIM + k]);
    }
    for (int i = i0; i < G4; i += stride) {
        int s = perm_src_row(i);
        d_bsum[i] = bih[s] + bhh[s];
    }
    for (int i = i0; i < BATCH * HDIM; i += stride)
        d_h16[0][i] = __float2half(h0[i]);
    for (int i = i0; i < T_STEPS * BATCH; i += stride)
        d_sum[i] = 0.0f;
}

// ---------------- phase 1: xproj (fp16 output) ----------------
__global__ __launch_bounds__(XTHREADS) void xproj_kernel()
{
    extern __shared__ __align__(16) char xsmem_raw[];
    __half* sAll = (__half*)xsmem_raw;
    __half* sA = sAll;
    __half* sB = sAll + STAGES * TILEHALFS;

    const int tid  = threadIdx.x;
    const int lane = tid & 31, wid = tid >> 5;
    const int wm = wid >> 1, wn = wid & 1;
    const int gq = lane >> 2, tq = lane & 3;
    const int fp = fperm(gq);
    const int n0 = blockIdx.x * 64;
    const int m0 = blockIdx.y * 64;

    const int lrow = tid >> 2, lch = tid & 3;
    const int fp_s = fperm(lrow);
    const uint32_t sAu = smem_u32(sA), sBu = smem_u32(sB);
    const uint32_t d0 = (uint32_t)(lrow * KT + ((lch ^ fp_s) * 8)) * 2;
    const uint32_t d1 = (uint32_t)(lrow * KT + (((lch + 4) ^ fp_s) * 8)) * 2;
    const int scol = lch * 8;

    const __half* Ag = d_in16  + (size_t)(m0 + lrow) * XDIM + scol;
    const __half* Bg = d_wih16 + (size_t)(n0 + lrow) * XDIM + scol;

    float acc[4][4];
    #pragma unroll
    for (int i = 0; i < 4; i++)
        #pragma unroll
        for (int j = 0; j < 4; j++) acc[i][j] = 0.0f;

    const int NITX = XDIM / KT;
    #pragma unroll
    for (int st = 0; st < 3; ++st) {
        const int kb = st * KT;
        CP16(sAu + (uint32_t)st * TILEHALFS * 2 + d0, Ag + kb);
        CP16(sAu + (uint32_t)st * TILEHALFS * 2 + d1, Ag + kb + 32);
        CP16(sBu + (uint32_t)st * TILEHALFS * 2 + d0, Bg + kb);
        CP16(sBu + (uint32_t)st * TILEHALFS * 2 + d1, Bg + kb + 32);
        CP_COMMIT();
    }

    const int rowA = wm * 16 + gq;
    #pragma unroll 1
    for (int it = 0; it < NITX; ++it) {
        CP_WAIT2();
        __syncthreads();
        const __half* At = sA + (it & 3) * TILEHALFS;
        const __half* Bt = sB + (it & 3) * TILEHALFS;
        #pragma unroll
        for (int k = 0; k < 4; ++k) {
            const int c0o = ((2 * k) ^ fp) * 8 + tq * 2;
            const int c1o = ((2 * k + 1) ^ fp) * 8 + tq * 2;
            uint32_t a0 = *(const uint32_t*)(At + rowA * KT + c0o);
            uint32_t a1 = *(const uint32_t*)(At + (rowA + 8) * KT + c0o);
            uint32_t a2 = *(const uint32_t*)(At + rowA * KT + c1o);
            uint32_t a3 = *(const uint32_t*)(At + (rowA + 8) * KT + c1o);
            #pragma unroll
            for (int nf = 0; nf < 4; nf++) {
                const int rowB = wn * 32 + nf * 8 + gq;
                uint32_t b0 = *(const uint32_t*)(Bt + rowB * KT + c0o);
                uint32_t b1 = *(const uint32_t*)(Bt + rowB * KT + c1o);
                mma16816(acc[nf], a0, a1, a2, a3, b0, b1);
            }
        }
        __syncthreads();
        const int nxt = it + 3;
        if (nxt < NITX) {
            const uint32_t so = (uint32_t)(nxt & 3) * TILEHALFS * 2;
            const int kb = nxt * KT;
            CP16(sAu + so + d0, Ag + kb);
            CP16(sAu + so + d1, Ag + kb + 32);
            CP16(sBu + so + d0, Bg + kb);
            CP16(sBu + so + d1, Bg + kb + 32);
        }
        CP_COMMIT();
    }

    #pragma unroll
    for (int nf = 0; nf < 4; nf++) {
        const int cb = n0 + wn * 32 + nf * 8 + tq * 2;
        const int r0 = m0 + wm * 16 + gq;
        float2 bsv = *(const float2*)(d_bsum + cb);
        __half2 v0 = __floats2half2_rn(acc[nf][0] + bsv.x, acc[nf][1] + bsv.y);
        __half2 v1 = __floats2half2_rn(acc[nf][2] + bsv.x, acc[nf][3] + bsv.y);
        *(__half2*)(d_xproj + (size_t)r0 * G4 + cb)       = v0;
        *(__half2*)(d_xproj + (size_t)(r0 + 8) * G4 + cb) = v1;
    }
}

// ---------------- grid barrier (128 CTAs co-resident) ----------------
__device__ __forceinline__ void grid_barrier(unsigned target)
{
    __syncthreads();
    if (threadIdx.x == 0) {
        __threadfence();
        atomicAdd(&d_bar, 1u);
        volatile unsigned* p = &d_bar;
        while (*p < target) { }
        __threadfence();
    }
    __syncthreads();
}

// ---------------- phase 2: persistent recurrent kernel ----------------
__global__ __launch_bounds__(PTHREADS, 1) void lstm_persistent_c0(
    float* __restrict__ out, const float* __restrict__ c0)
{
    extern __shared__ __align__(1024) char smem_raw[];
    const uint32_t sbase = smem_u32(smem_raw);
    __half* gsum = (__half*)(smem_raw + OFF_GSUM);

    const int cta  = blockIdx.x;
    const int tid  = threadIdx.x;
    const int lane = tid & 31;
    const int g    = tid >> 8;              // K-half group (0,1)
    const int gtid = tid & 255;
    const int gwid = gtid >> 5;             // warp in group 0..7
    const int wm = gwid & 1;                // m half (batch 32)
    const int wn = (gwid >> 1) & 1;         // n half (gate 32)
    const int wk = gwid >> 2;               // k quarter within group
    const int gq = lane >> 2, tq = lane & 3;
    const int n0 = cta * 64;                // permuted gate-row base
    const int KOFF = g * (HDIM / 2);
    const int NIT  = (HDIM / 2) / KT;       // 16

    const uint32_t aGrp = sbase + (uint32_t)g * PSTAGES * ASTG;
    const uint32_t bGrp = sbase + OFF_SB + (uint32_t)g * PSTAGES * ASTG;

    const int lrow = gtid >> 2, lch = gtid & 3;
    const int fp_s = fperm(lrow);
    const uint32_t d0 = (uint32_t)(lrow * 128 + ((lch ^ fp_s) << 4));
    const uint32_t d1 = (uint32_t)(lrow * 128 + (((lch + 4) ^ fp_s) << 4));
    const int scol = lch * 8;
    const __half* Bg = d_whh16 + (size_t)(n0 + lrow) * HDIM + KOFF + scol;

    const int fp_l = fperm(lane & 7);
    const uint32_t rowA0 = (uint32_t)((wm * 32 + (lane & 15)) * 128);
    const uint32_t rowA1 = rowA0 + 16 * 128;
    const uint32_t rowB0 = (uint32_t)((wn * 32 + ((lane >> 4) & 1) * 8 + (lane & 7)) * 128);
    const uint32_t rowB1 = rowB0 + 16 * 128;
    const int khA = (lane >> 4) & 1;
    const int khB = (lane >> 3) & 1;
    const int kb16 = wk * 2;

    const size_t HOFF = (size_t)T_STEPS * BATCH * HDIM;
    const size_t COFF = HOFF + (size_t)BATCH * HDIM;

    const int b1 = tid >> 4,        jj1 = tid & 15;
    const int b2 = 32 + (tid >> 4), jj2 = jj1;
    float creg1 = c0[b1 * HDIM + cta * 16 + jj1];
    float creg2 = c0[b2 * HDIM + cta * 16 + jj2];

    unsigned bar_target = 0;

#define ISSUE(SLOT, KB, HB) do {                                              \
        const __half* asrc_ = (HB) + (size_t)lrow * HDIM + KOFF + (KB) + scol;\
        const __half* bsrc_ = Bg + (KB);                                      \
        const uint32_t ao_ = aGrp + (uint32_t)(SLOT) * ASTG;                  \
        const uint32_t bo_ = bGrp + (uint32_t)(SLOT) * ASTG;                  \
        CP16(ao_ + d0, asrc_);                                                \
        CP16(ao_ + d1, asrc_ + 32);                                           \
        CP16(bo_ + d0, bsrc_);                                                \
        CP16(bo_ + d1, bsrc_ + 32);                                           \
        CP_COMMIT();                                                          \
    } while (0)

    // initial prologue: 5 stages of step 0
    {
        const __half* hbuf = d_h16[0];
        #pragma unroll
        for (int st = 0; st < 5; ++st) ISSUE(st, st * KT, hbuf);
    }

    #pragma unroll 1
    for (int t = 0; t < T_STEPS; ++t) {
        const __half* hbuf = d_h16[t & 1];

        // prefetch this step's xproj gate values (fp16, hidden behind GEMM)
        const __half* xp = d_xproj + (size_t)t * BATCH * G4 + n0;
        const __half* xr1 = xp + (size_t)b1 * G4;
        const __half* xr2 = xp + (size_t)b2 * G4;
        float xv1[4], xv2[4];
        #pragma unroll
        for (int q = 0; q < 4; ++q) {
            xv1[q] = __half2float(xr1[q * 16 + jj1]);
            xv2[q] = __half2float(xr2[q * 16 + jj2]);
        }

        float acc[2][4][4];
        #pragma unroll
        for (int i = 0; i < 2; i++)
            #pragma unroll
            for (int j = 0; j < 4; j++)
                #pragma unroll
                for (int q = 0; q < 4; q++) acc[i][j][q] = 0.0f;

        // FULLY UNROLLED: slot indices are compile-time constants
        #pragma unroll
        for (int it = 0; it < NIT; ++it) {
            const int slot = it % PSTAGES;          // const-folded
            CP_WAIT4();
            asm volatile("bar.sync %0, 256;\n" :: "r"(g + 1) : "memory");
            const uint32_t At = aGrp + (uint32_t)(slot * ASTG);
            const uint32_t Bt = bGrp + (uint32_t)(slot * ASTG);
            #pragma unroll
            for (int kc = 0; kc < 2; ++kc) {
                const uint32_t ccA = (uint32_t)((((kb16 + kc) << 1) | khA) ^ fp_l) << 4;
                const uint32_t ccB = (uint32_t)((((kb16 + kc) << 1) | khB) ^ fp_l) << 4;
                uint32_t a0[4], a1[4], bb0[4], bb1[4];
                LDSM4(a0[0], a0[1], a0[2], a0[3], At + rowA0 + ccA);
                LDSM4(a1[0], a1[1], a1[2], a1[3], At + rowA1 + ccA);
                LDSM4(bb0[0], bb0[1], bb0[2], bb0[3], Bt + rowB0 + ccB);
                LDSM4(bb1[0], bb1[1], bb1[2], bb1[3], Bt + rowB1 + ccB);
                mma16816(acc[0][0], a0[0], a0[1], a0[2], a0[3], bb0[0], bb0[1]);
                mma16816(acc[0][1], a0[0], a0[1], a0[2], a0[3], bb0[2], bb0[3]);
                mma16816(acc[0][2], a0[0], a0[1], a0[2], a0[3], bb1[0], bb1[1]);
                mma16816(acc[0][3], a0[0], a0[1], a0[2], a0[3], bb1[2], bb1[3]);
                mma16816(acc[1][0], a1[0], a1[1], a1[2], a1[3], bb0[0], bb0[1]);
                mma16816(acc[1][1], a1[0], a1[1], a1[2], a1[3], bb0[2], bb0[3]);
                mma16816(acc[1][2], a1[0], a1[1], a1[2], a1[3], bb1[0], bb1[1]);
                mma16816(acc[1][3], a1[0], a1[1], a1[2], a1[3], bb1[2], bb1[3]);
            }
            if (it + 5 < NIT) {
                const int wslot = (it + 5) % PSTAGES;   // const-folded
                ISSUE(wslot, (it + 5) * KT, hbuf);
            } else {
                CP_COMMIT();
            }
        }

        // epilogue: write this warp's partial slab in fp16 (slab = g*2 + wk)
        {
            __half* gs = gsum + (size_t)(g * 2 + wk) * GSLAB;
            #pragma unroll
            for (int mf = 0; mf < 2; ++mf) {
                const int row = wm * 32 + mf * 16 + gq;
                #pragma unroll
                for (int nf = 0; nf < 4; ++nf) {
                    const int col = wn * 32 + nf * 8 + tq * 2;
                    *(__half2*)&gs[row * GSTR + col] =
                        __floats2half2_rn(acc[mf][nf][0], acc[mf][nf][1]);
                    *(__half2*)&gs[(row + 8) * GSTR + col] =
                        __floats2half2_rn(acc[mf][nf][2], acc[mf][nf][3]);
                }
            }
        }
        __syncthreads();

        // pointwise LSTM + exp + partial softmax sum
        __half* hN = d_h16[(t + 1) & 1];
        float e1, e2;
        {
            const __half* gb = gsum + (size_t)b1 * GSTR;
            float ip = __half2float(gb[jj1]) + __half2float(gb[GSLAB + jj1])
                     + __half2float(gb[2*GSLAB + jj1]) + __half2float(gb[3*GSLAB + jj1]) + xv1[0];
            float fpv= __half2float(gb[16+jj1]) + __half2float(gb[GSLAB+16+jj1])
                     + __half2float(gb[2*GSLAB+16+jj1]) + __half2float(gb[3*GSLAB+16+jj1]) + xv1[1];
            float gp = __half2float(gb[32+jj1]) + __half2float(gb[GSLAB+32+jj1])
                     + __half2float(gb[2*GSLAB+32+jj1]) + __half2float(gb[3*GSLAB+32+jj1]) + xv1[2];
            float op = __half2float(gb[48+jj1]) + __half2float(gb[GSLAB+48+jj1])
                     + __half2float(gb[2*GSLAB+48+jj1]) + __half2float(gb[3*GSLAB+48+jj1]) + xv1[3];
            float ii = sigmoid_hw(ip), ff = sigmoid_hw(fpv);
            float gg = tanh_hw(gp),    oo = sigmoid_hw(op);
            float cn = ff * creg1 + ii * gg;
            creg1 = cn;
            float hn = oo * tanh_hw(cn);
            hN[b1 * HDIM + cta * 16 + jj1] = __float2half(hn);
            if (t == T_STEPS - 1) {
                out[HOFF + (size_t)b1 * HDIM + cta * 16 + jj1] = hn;
                out[COFF + (size_t)b1 * HDIM + cta * 16 + jj1] = cn;
            }
            e1 = exp_hw(hn);
        }
        {
            const __half* gb = gsum + (size_t)b2 * GSTR;
            float ip = __half2float(gb[jj2]) + __half2float(gb[GSLAB + jj2])
                     + __half2float(gb[2*GSLAB + jj2]) + __half2float(gb[3*GSLAB + jj2]) + xv2[0];
            float fpv= __half2float(gb[16+jj2]) + __half2float(gb[GSLAB+16+jj2])
                     + __half2float(gb[2*GSLAB+16+jj2]) + __half2float(gb[3*GSLAB+16+jj2]) + xv2[1];
            float gp = __half2float(gb[32+jj2]) + __half2float(gb[GSLAB+32+jj2])
                     + __half2float(gb[2*GSLAB+32+jj2]) + __half2float(gb[3*GSLAB+32+jj2]) + xv2[2];
            float op = __half2float(gb[48+jj2]) + __half2float(gb[GSLAB+48+jj2])
                     + __half2float(gb[2*GSLAB+48+jj2]) + __half2float(gb[3*GSLAB+48+jj2]) + xv2[3];
            float ii = sigmoid_hw(ip), ff = sigmoid_hw(fpv);
            float gg = tanh_hw(gp),    oo = sigmoid_hw(op);
            float cn = ff * creg2 + ii * gg;
            creg2 = cn;
            float hn = oo * tanh_hw(cn);
            hN[b2 * HDIM + cta * 16 + jj2] = __float2half(hn);
            if (t == T_STEPS - 1) {
                out[HOFF + (size_t)b2 * HDIM + cta * 16 + jj2] = hn;
                out[COFF + (size_t)b2 * HDIM + cta * 16 + jj2] = cn;
            }
            e2 = exp_hw(hn);
        }
        float v1 = e1, v2 = e2;
        #pragma unroll
        for (int o = 8; o > 0; o >>= 1) {
            v1 += __shfl_xor_sync(0xffffffffu, v1, o);
            v2 += __shfl_xor_sync(0xffffffffu, v2, o);
        }
        if ((lane & 15) == 0) {
            atomicAdd(&d_sum[t * BATCH + b1], v1);
            atomicAdd(&d_sum[t * BATCH + b2], v2);
        }

        bar_target += NCTAS;
        grid_barrier(bar_target);

        // d_sum loads first (overlap with prologue issuance), then prologue
        float s1 = __ldcg(&d_sum[t * BATCH + b1]);
        float s2 = __ldcg(&d_sum[t * BATCH + b2]);
        if (t + 1 < T_STEPS) {
            const __half* hnext = d_h16[(t + 1) & 1];
            #pragma unroll
            for (int st = 0; st < 5; ++st) ISSUE(st, st * KT, hnext);
        }
        {
            out[(size_t)t * BATCH * HDIM + (size_t)b1 * HDIM + cta * 16 + jj1] = e1 * (1.0f / s1);
            out[(size_t)t * BATCH * HDIM + (size_t)b2 * HDIM + cta * 16 + jj2] = e2 * (1.0f / s2);
        }
    }
#undef ISSUE
}

// ---------------- entry ----------------
extern "C" void kernel_launch(void* const* d_in, const int* in_sizes, int n_in,
                              void* d_out, int out_size)
{
    (void)in_sizes; (void)n_in; (void)out_size;
    const float* input = (const float*)d_in[0];
    const float* h0    = (const float*)d_in[1];
    const float* c0    = (const float*)d_in[2];
    const float* wih   = (const float*)d_in[3];
    const float* whh   = (const float*)d_in[4];
    const float* bih   = (const float*)d_in[5];
    const float* bhh   = (const float*)d_in[6];

    const int xsmem = 2 * STAGES * TILEHALFS * (int)sizeof(__half);
    cudaFuncSetAttribute(xproj_kernel,
                         cudaFuncAttributeMaxDynamicSharedMemorySize, xsmem);
    cudaFuncSetAttribute(lstm_persistent_c0,
                         cudaFuncAttributeMaxDynamicSharedMemorySize, PSMEM);

    prep_kernel<<<1024, 256>>>(input, h0, c0, wih, whh, bih, bhh);
    xproj_kernel<<<dim3(G4 / 64, (T_STEPS * BATCH) / 64), XTHREADS, xsmem>>>();
    lstm_persistent_c0<<<NCTAS, PTHREADS, PSMEM>>>((float*)d_out, c0);
}

// round 11
// speedup vs baseline: 1.0562x; 1.0082x over previous
#include <cuda_runtime.h>
#include <cuda_fp16.h>
#include <cstdint>

#define T_STEPS 256
#define BATCH   64
#define XDIM    512
#define HDIM    2048
#define G4      8192
#define NCTAS   128
#define PTHREADS 512
#define XTHREADS 256
#define KT      64                 // K-tile per stage (halfs) = 128 B rows
#define TILEHALFS (64*KT)
#define STAGES  4                  // xproj stages
#define PSTAGES 6                  // persistent-kernel stages
#define ASTG    8192               // stage tile bytes (64 rows * 128 B)
#define GSTR    68                 // gsum row stride (halfs)
#define GSLAB   (64*GSTR)          // halfs per slab

// persistent smem layout (bytes)
#define OFF_SB   (2*PSTAGES*ASTG)            // 98304  (A: 2 groups * 6 stages)
#define OFF_GSUM (OFF_SB + 2*PSTAGES*ASTG)   // 196608 (B same size)
#define PSMEM    (OFF_GSUM + 4*GSLAB*2)      // + 4 fp16 slabs = 231424 B

// ---------------- device scratch ----------------
__device__ __align__(16) __half d_in16 [T_STEPS * BATCH * XDIM];
__device__ __align__(16) __half d_wih16[G4 * XDIM];
__device__ __align__(16) __half d_whh16[G4 * HDIM];
__device__ __align__(16) float  d_bsum [G4];
__device__ __align__(16) __half d_xproj[(size_t)T_STEPS * BATCH * G4];  // fp16
__device__ __align__(16) __half d_h16  [2][BATCH * HDIM];
__device__ __align__(16) float  d_sum  [T_STEPS * BATCH];
__device__ unsigned d_bar;

// ---------------- helpers ----------------
__device__ __forceinline__ void mma16816(float* c,
    uint32_t a0, uint32_t a1, uint32_t a2, uint32_t a3,
    uint32_t b0, uint32_t b1)
{
    asm volatile(
        "mma.sync.aligned.m16n8k16.row.col.f32.f16.f16.f32 "
        "{%0,%1,%2,%3},{%4,%5,%6,%7},{%8,%9},{%0,%1,%2,%3};\n"
        : "+f"(c[0]), "+f"(c[1]), "+f"(c[2]), "+f"(c[3])
        : "r"(a0), "r"(a1), "r"(a2), "r"(a3), "r"(b0), "r"(b1));
}
#define LDSM4(r0, r1, r2, r3, addr) \
    asm volatile("ldmatrix.sync.aligned.m8n8.x4.shared.b16 {%0,%1,%2,%3}, [%4];" \
        : "=r"(r0), "=r"(r1), "=r"(r2), "=r"(r3) : "r"(addr))

__device__ __forceinline__ float tanh_hw(float x) {
    float y;
    asm("tanh.approx.f32 %0, %1;" : "=f"(y) : "f"(x));
    return y;
}
__device__ __forceinline__ float sigmoid_hw(float x) {
    return fmaf(tanh_hw(0.5f * x), 0.5f, 0.5f);
}
__device__ __forceinline__ float exp_hw(float x) {
    float y;
    asm("ex2.approx.ftz.f32 %0, %1;" : "=f"(y) : "f"(x * 1.4426950408889634f));
    return y;
}

__device__ __forceinline__ uint32_t smem_u32(const void* p) {
    return (uint32_t)__cvta_generic_to_shared(p);
}
__device__ __forceinline__ int fperm(int r) { return ((r & 1) << 2) | ((r & 7) >> 1); }

#define CP16(dst_u32, src_ptr) \
    asm volatile("cp.async.cg.shared.global [%0], [%1], 16;\n" :: "r"(dst_u32), "l"(src_ptr))
#define CP_COMMIT() asm volatile("cp.async.commit_group;\n" ::: "memory")
#define CP_WAIT2()  asm volatile("cp.async.wait_group 2;\n" ::: "memory")
#define CP_WAIT4()  asm volatile("cp.async.wait_group 4;\n" ::: "memory")

// row permutation: dst row (CTA-major: cta*64 + gate*16 + jj) -> src gate row
__device__ __forceinline__ int perm_src_row(int r) {
    int cta = r >> 6;
    int ln  = r & 63;
    int gate = ln >> 4;
    int jj   = ln & 15;
    return gate * HDIM + cta * 16 + jj;
}

// ---------------- phase 0 ----------------
__global__ __launch_bounds__(256) void prep_kernel(
    const float* __restrict__ input, const float* __restrict__ h0,
    const float* __restrict__ c0,    const float* __restrict__ wih,
    const float* __restrict__ whh,   const float* __restrict__ bih,
    const float* __restrict__ bhh)
{
    (void)c0;
    const int i0 = blockIdx.x * blockDim.x + threadIdx.x;
    const int stride = gridDim.x * blockDim.x;
    if (i0 == 0) d_bar = 0u;
    for (int i = i0; i < T_STEPS * BATCH * XDIM; i += stride)
        d_in16[i] = __float2half(input[i]);
    for (int i = i0; i < G4 * XDIM; i += stride) {
        int r = i >> 9, k = i & (XDIM - 1);
        d_wih16[i] = __float2half(wih[perm_src_row(r) * XDIM + k]);
    }
    for (int i = i0; i < G4 * HDIM; i += stride) {
        int r = i >> 11, k = i & (HDIM - 1);
        d_whh16[i] = __float2half(whh[(size_t)perm_src_row(r) * HDIM + k]);
    }
    for (int i = i0; i < G4; i += stride) {
        int s = perm_src_row(i);
        d_bsum[i] = bih[s] + bhh[s];
    }
    for (int i = i0; i < BATCH * HDIM; i += stride)
        d_h16[0][i] = __float2half(h0[i]);
    for (int i = i0; i < T_STEPS * BATCH; i += stride)
        d_sum[i] = 0.0f;
}

// ---------------- phase 1: xproj (fp16 output) ----------------
__global__ __launch_bounds__(XTHREADS) void xproj_kernel()
{
    extern __shared__ __align__(16) char xsmem_raw[];
    __half* sAll = (__half*)xsmem_raw;
    __half* sA = sAll;
    __half* sB = sAll + STAGES * TILEHALFS;

    const int tid  = threadIdx.x;
    const int lane = tid & 31, wid = tid >> 5;
    const int wm = wid >> 1, wn = wid & 1;
    const int gq = lane >> 2, tq = lane & 3;
    const int fp = fperm(gq);
    const int n0 = blockIdx.x * 64;
    const int m0 = blockIdx.y * 64;

    const int lrow = tid >> 2, lch = tid & 3;
    const int fp_s = fperm(lrow);
    const uint32_t sAu = smem_u32(sA), sBu = smem_u32(sB);
    const uint32_t d0 = (uint32_t)(lrow * KT + ((lch ^ fp_s) * 8)) * 2;
    const uint32_t d1 = (uint32_t)(lrow * KT + (((lch + 4) ^ fp_s) * 8)) * 2;
    const int scol = lch * 8;

    const __half* Ag = d_in16  + (size_t)(m0 + lrow) * XDIM + scol;
    const __half* Bg = d_wih16 + (size_t)(n0 + lrow) * XDIM + scol;

    float acc[4][4];
    #pragma unroll
    for (int i = 0; i < 4; i++)
        #pragma unroll
        for (int j = 0; j < 4; j++) acc[i][j] = 0.0f;

    const int NITX = XDIM / KT;
    #pragma unroll
    for (int st = 0; st < 3; ++st) {
        const int kb = st * KT;
        CP16(sAu + (uint32_t)st * TILEHALFS * 2 + d0, Ag + kb);
        CP16(sAu + (uint32_t)st * TILEHALFS * 2 + d1, Ag + kb + 32);
        CP16(sBu + (uint32_t)st * TILEHALFS * 2 + d0, Bg + kb);
        CP16(sBu + (uint32_t)st * TILEHALFS * 2 + d1, Bg + kb + 32);
        CP_COMMIT();
    }

    const int rowA = wm * 16 + gq;
    #pragma unroll 1
    for (int it = 0; it < NITX; ++it) {
        CP_WAIT2();
        __syncthreads();
        const __half* At = sA + (it & 3) * TILEHALFS;
        const __half* Bt = sB + (it & 3) * TILEHALFS;
        #pragma unroll
        for (int k = 0; k < 4; ++k) {
            const int c0o = ((2 * k) ^ fp) * 8 + tq * 2;
            const int c1o = ((2 * k + 1) ^ fp) * 8 + tq * 2;
            uint32_t a0 = *(const uint32_t*)(At + rowA * KT + c0o);
            uint32_t a1 = *(const uint32_t*)(At + (rowA + 8) * KT + c0o);
            uint32_t a2 = *(const uint32_t*)(At + rowA * KT + c1o);
            uint32_t a3 = *(const uint32_t*)(At + (rowA + 8) * KT + c1o);
            #pragma unroll
            for (int nf = 0; nf < 4; nf++) {
                const int rowB = wn * 32 + nf * 8 + gq;
                uint32_t b0 = *(const uint32_t*)(Bt + rowB * KT + c0o);
                uint32_t b1 = *(const uint32_t*)(Bt + rowB * KT + c1o);
                mma16816(acc[nf], a0, a1, a2, a3, b0, b1);
            }
        }
        __syncthreads();
        const int nxt = it + 3;
        if (nxt < NITX) {
            const uint32_t so = (uint32_t)(nxt & 3) * TILEHALFS * 2;
            const int kb = nxt * KT;
            CP16(sAu + so + d0, Ag + kb);
            CP16(sAu + so + d1, Ag + kb + 32);
            CP16(sBu + so + d0, Bg + kb);
            CP16(sBu + so + d1, Bg + kb + 32);
        }
        CP_COMMIT();
    }

    #pragma unroll
    for (int nf = 0; nf < 4; nf++) {
        const int cb = n0 + wn * 32 + nf * 8 + tq * 2;
        const int r0 = m0 + wm * 16 + gq;
        float2 bsv = *(const float2*)(d_bsum + cb);
        __half2 v0 = __floats2half2_rn(acc[nf][0] + bsv.x, acc[nf][1] + bsv.y);
        __half2 v1 = __floats2half2_rn(acc[nf][2] + bsv.x, acc[nf][3] + bsv.y);
        *(__half2*)(d_xproj + (size_t)r0 * G4 + cb)       = v0;
        *(__half2*)(d_xproj + (size_t)(r0 + 8) * G4 + cb) = v1;
    }
}

// ---------------- grid barrier (128 CTAs co-resident) ----------------
__device__ __forceinline__ void grid_barrier(unsigned target)
{
    __syncthreads();
    if (threadIdx.x == 0) {
        __threadfence();
        atomicAdd(&d_bar, 1u);
        volatile unsigned* p = &d_bar;
        while (*p < target) { }
        __threadfence();
    }
    __syncthreads();
}

// ---------------- phase 2: persistent recurrent kernel ----------------
__global__ __launch_bounds__(PTHREADS, 1) void lstm_persistent_c0(
    float* __restrict__ out, const float* __restrict__ c0)
{
    extern __shared__ __align__(1024) char smem_raw[];
    const uint32_t sbase = smem_u32(smem_raw);
    __half* gsum = (__half*)(smem_raw + OFF_GSUM);

    const int cta  = blockIdx.x;
    const int tid  = threadIdx.x;
    const int lane = tid & 31;
    const int g    = tid >> 8;              // K-half group (0,1)
    const int gtid = tid & 255;
    const int gwid = gtid >> 5;             // warp in group 0..7
    const int wm = gwid & 1;                // m half (batch 32)
    const int wn = (gwid >> 1) & 1;         // n half (gate 32)
    const int wk = gwid >> 2;               // k quarter within group
    const int gq = lane >> 2, tq = lane & 3;
    const int n0 = cta * 64;                // permuted gate-row base
    const int KOFF = g * (HDIM / 2);
    const int NIT  = (HDIM / 2) / KT;       // 16

    const uint32_t aGrp = sbase + (uint32_t)g * PSTAGES * ASTG;
    const uint32_t bGrp = sbase + OFF_SB + (uint32_t)g * PSTAGES * ASTG;

    const int lrow = gtid >> 2, lch = gtid & 3;
    const int fp_s = fperm(lrow);
    const uint32_t d0 = (uint32_t)(lrow * 128 + ((lch ^ fp_s) << 4));
    const uint32_t d1 = (uint32_t)(lrow * 128 + (((lch + 4) ^ fp_s) << 4));
    const int scol = lch * 8;
    const __half* Bg = d_whh16 + (size_t)(n0 + lrow) * HDIM + KOFF + scol;

    const int fp_l = fperm(lane & 7);
    const uint32_t rowA0 = (uint32_t)((wm * 32 + (lane & 15)) * 128);
    const uint32_t rowA1 = rowA0 + 16 * 128;
    const uint32_t rowB0 = (uint32_t)((wn * 32 + ((lane >> 4) & 1) * 8 + (lane & 7)) * 128);
    const uint32_t rowB1 = rowB0 + 16 * 128;
    const int khA = (lane >> 4) & 1;
    const int khB = (lane >> 3) & 1;
    const int kb16 = wk * 2;

    const size_t HOFF = (size_t)T_STEPS * BATCH * HDIM;
    const size_t COFF = HOFF + (size_t)BATCH * HDIM;

    const int b1 = tid >> 4,        jj1 = tid & 15;
    const int b2 = 32 + (tid >> 4), jj2 = jj1;
    float creg1 = c0[b1 * HDIM + cta * 16 + jj1];
    float creg2 = c0[b2 * HDIM + cta * 16 + jj2];

    // deferred-softmax carry: previous step's exp values
    float pe1 = 0.0f, pe2 = 0.0f;

    unsigned bar_target = 0;

#define ISSUE(SLOT, KB, HB) do {                                              \
        const __half* asrc_ = (HB) + (size_t)lrow * HDIM + KOFF + (KB) + scol;\
        const __half* bsrc_ = Bg + (KB);                                      \
        const uint32_t ao_ = aGrp + (uint32_t)(SLOT) * ASTG;                  \
        const uint32_t bo_ = bGrp + (uint32_t)(SLOT) * ASTG;                  \
        CP16(ao_ + d0, asrc_);                                                \
        CP16(ao_ + d1, asrc_ + 32);                                           \
        CP16(bo_ + d0, bsrc_);                                                \
        CP16(bo_ + d1, bsrc_ + 32);                                           \
        CP_COMMIT();                                                          \
    } while (0)

    // initial prologue: 5 stages of step 0
    {
        const __half* hbuf = d_h16[0];
        #pragma unroll
        for (int st = 0; st < 5; ++st) ISSUE(st, st * KT, hbuf);
    }

    #pragma unroll 1
    for (int t = 0; t < T_STEPS; ++t) {
        const __half* hbuf = d_h16[t & 1];

        // prefetch this step's xproj gate values (fp16, hidden behind GEMM)
        const __half* xp = d_xproj + (size_t)t * BATCH * G4 + n0;
        const __half* xr1 = xp + (size_t)b1 * G4;
        const __half* xr2 = xp + (size_t)b2 * G4;
        float xv1[4], xv2[4];
        #pragma unroll
        for (int q = 0; q < 4; ++q) {
            xv1[q] = __half2float(xr1[q * 16 + jj1]);
            xv2[q] = __half2float(xr2[q * 16 + jj2]);
        }

        float acc[2][4][4];
        #pragma unroll
        for (int i = 0; i < 2; i++)
            #pragma unroll
            for (int j = 0; j < 4; j++)
                #pragma unroll
                for (int q = 0; q < 4; q++) acc[i][j][q] = 0.0f;

        // FULLY UNROLLED: slot indices are compile-time constants
        #pragma unroll
        for (int it = 0; it < NIT; ++it) {
            const int slot = it % PSTAGES;          // const-folded
            CP_WAIT4();
            asm volatile("bar.sync %0, 256;\n" :: "r"(g + 1) : "memory");
            const uint32_t At = aGrp + (uint32_t)(slot * ASTG);
            const uint32_t Bt = bGrp + (uint32_t)(slot * ASTG);
            #pragma unroll
            for (int kc = 0; kc < 2; ++kc) {
                const uint32_t ccA = (uint32_t)((((kb16 + kc) << 1) | khA) ^ fp_l) << 4;
                const uint32_t ccB = (uint32_t)((((kb16 + kc) << 1) | khB) ^ fp_l) << 4;
                uint32_t a0[4], a1[4], bb0[4], bb1[4];
                LDSM4(a0[0], a0[1], a0[2], a0[3], At + rowA0 + ccA);
                LDSM4(a1[0], a1[1], a1[2], a1[3], At + rowA1 + ccA);
                LDSM4(bb0[0], bb0[1], bb0[2], bb0[3], Bt + rowB0 + ccB);
                LDSM4(bb1[0], bb1[1], bb1[2], bb1[3], Bt + rowB1 + ccB);
                mma16816(acc[0][0], a0[0], a0[1], a0[2], a0[3], bb0[0], bb0[1]);
                mma16816(acc[0][1], a0[0], a0[1], a0[2], a0[3], bb0[2], bb0[3]);
                mma16816(acc[0][2], a0[0], a0[1], a0[2], a0[3], bb1[0], bb1[1]);
                mma16816(acc[0][3], a0[0], a0[1], a0[2], a0[3], bb1[2], bb1[3]);
                mma16816(acc[1][0], a1[0], a1[1], a1[2], a1[3], bb0[0], bb0[1]);
                mma16816(acc[1][1], a1[0], a1[1], a1[2], a1[3], bb0[2], bb0[3]);
                mma16816(acc[1][2], a1[0], a1[1], a1[2], a1[3], bb1[0], bb1[1]);
                mma16816(acc[1][3], a1[0], a1[1], a1[2], a1[3], bb1[2], bb1[3]);
            }
            if (it + 5 < NIT) {
                const int wslot = (it + 5) % PSTAGES;   // const-folded
                ISSUE(wslot, (it + 5) * KT, hbuf);
            } else {
                CP_COMMIT();
            }
        }

        // epilogue: write this warp's partial slab in fp16 (slab = g*2 + wk)
        {
            __half* gs = gsum + (size_t)(g * 2 + wk) * GSLAB;
            #pragma unroll
            for (int mf = 0; mf < 2; ++mf) {
                const int row = wm * 32 + mf * 16 + gq;
                #pragma unroll
                for (int nf = 0; nf < 4; ++nf) {
                    const int col = wn * 32 + nf * 8 + tq * 2;
                    *(__half2*)&gs[row * GSTR + col] =
                        __floats2half2_rn(acc[mf][nf][0], acc[mf][nf][1]);
                    *(__half2*)&gs[(row + 8) * GSTR + col] =
                        __floats2half2_rn(acc[mf][nf][2], acc[mf][nf][3]);
                }
            }
        }
        __syncthreads();

        // pointwise LSTM + exp (softmax sum DEFERRED past the barrier)
        __half* hN = d_h16[(t + 1) & 1];
        float e1, e2;
        {
            const __half* gb = gsum + (size_t)b1 * GSTR;
            float ip = __half2float(gb[jj1]) + __half2float(gb[GSLAB + jj1])
                     + __half2float(gb[2*GSLAB + jj1]) + __half2float(gb[3*GSLAB + jj1]) + xv1[0];
            float fpv= __half2float(gb[16+jj1]) + __half2float(gb[GSLAB+16+jj1])
                     + __half2float(gb[2*GSLAB+16+jj1]) + __half2float(gb[3*GSLAB+16+jj1]) + xv1[1];
            float gp = __half2float(gb[32+jj1]) + __half2float(gb[GSLAB+32+jj1])
                     + __half2float(gb[2*GSLAB+32+jj1]) + __half2float(gb[3*GSLAB+32+jj1]) + xv1[2];
            float op = __half2float(gb[48+jj1]) + __half2float(gb[GSLAB+48+jj1])
                     + __half2float(gb[2*GSLAB+48+jj1]) + __half2float(gb[3*GSLAB+48+jj1]) + xv1[3];
            float ii = sigmoid_hw(ip), ff = sigmoid_hw(fpv);
            float gg = tanh_hw(gp),    oo = sigmoid_hw(op);
            float cn = ff * creg1 + ii * gg;
            creg1 = cn;
            float hn = oo * tanh_hw(cn);
            hN[b1 * HDIM + cta * 16 + jj1] = __float2half(hn);
            if (t == T_STEPS - 1) {
                out[HOFF + (size_t)b1 * HDIM + cta * 16 + jj1] = hn;
                out[COFF + (size_t)b1 * HDIM + cta * 16 + jj1] = cn;
            }
            e1 = exp_hw(hn);
        }
        {
            const __half* gb = gsum + (size_t)b2 * GSTR;
            float ip = __half2float(gb[jj2]) + __half2float(gb[GSLAB + jj2])
                     + __half2float(gb[2*GSLAB + jj2]) + __half2float(gb[3*GSLAB + jj2]) + xv2[0];
            float fpv= __half2float(gb[16+jj2]) + __half2float(gb[GSLAB+16+jj2])
                     + __half2float(gb[2*GSLAB+16+jj2]) + __half2float(gb[3*GSLAB+16+jj2]) + xv2[1];
            float gp = __half2float(gb[32+jj2]) + __half2float(gb[GSLAB+32+jj2])
                     + __half2float(gb[2*GSLAB+32+jj2]) + __half2float(gb[3*GSLAB+32+jj2]) + xv2[2];
            float op = __half2float(gb[48+jj2]) + __half2float(gb[GSLAB+48+jj2])
                     + __half2float(gb[2*GSLAB+48+jj2]) + __half2float(gb[3*GSLAB+48+jj2]) + xv2[3];
            float ii = sigmoid_hw(ip), ff = sigmoid_hw(fpv);
            float gg = tanh_hw(gp),    oo = sigmoid_hw(op);
            float cn = ff * creg2 + ii * gg;
            creg2 = cn;
            float hn = oo * tanh_hw(cn);
            hN[b2 * HDIM + cta * 16 + jj2] = __float2half(hn);
            if (t == T_STEPS - 1) {
                out[HOFF + (size_t)b2 * HDIM + cta * 16 + jj2] = hn;
                out[COFF + (size_t)b2 * HDIM + cta * 16 + jj2] = cn;
            }
            e2 = exp_hw(hn);
        }
        // shuffle-reduce partials (registers only, cheap) before the barrier
        float v1 = e1, v2 = e2;
        #pragma unroll
        for (int o = 8; o > 0; o >>= 1) {
            v1 += __shfl_xor_sync(0xffffffffu, v1, o);
            v2 += __shfl_xor_sync(0xffffffffu, v2, o);
        }

        bar_target += NCTAS;
        grid_barrier(bar_target);        // only h(t+1) visibility on critical path

        // 1) next step's prologue first (hide cp.async refill)
        if (t + 1 < T_STEPS) {
            const __half* hnext = d_h16[(t + 1) & 1];
            #pragma unroll
            for (int st = 0; st < 5; ++st) ISSUE(st, st * KT, hnext);
        }
        // 2) finish PREVIOUS step's softmax (atomics t-1 drained during GEMM(t))
        if (t > 0) {
            float s1 = __ldcg(&d_sum[(t - 1) * BATCH + b1]);
            float s2 = __ldcg(&d_sum[(t - 1) * BATCH + b2]);
            out[(size_t)(t - 1) * BATCH * HDIM + (size_t)b1 * HDIM + cta * 16 + jj1] = pe1 * (1.0f / s1);
            out[(size_t)(t - 1) * BATCH * HDIM + (size_t)b2 * HDIM + cta * 16 + jj2] = pe2 * (1.0f / s2);
        }
        // 3) THIS step's d_sum atomics — overlap with GEMM(t+1)
        if ((lane & 15) == 0) {
            atomicAdd(&d_sum[t * BATCH + b1], v1);
            atomicAdd(&d_sum[t * BATCH + b2], v2);
        }
        pe1 = e1;
        pe2 = e2;
    }

    // drain: final barrier guarantees step-255 atomics visible, then write y(255)
    bar_target += NCTAS;
    grid_barrier(bar_target);
    {
        float s1 = __ldcg(&d_sum[(T_STEPS - 1) * BATCH + b1]);
        float s2 = __ldcg(&d_sum[(T_STEPS - 1) * BATCH + b2]);
        out[(size_t)(T_STEPS - 1) * BATCH * HDIM + (size_t)b1 * HDIM + cta * 16 + jj1] = pe1 * (1.0f / s1);
        out[(size_t)(T_STEPS - 1) * BATCH * HDIM + (size_t)b2 * HDIM + cta * 16 + jj2] = pe2 * (1.0f / s2);
    }
#undef ISSUE
}

// ---------------- entry ----------------
extern "C" void kernel_launch(void* const* d_in, const int* in_sizes, int n_in,
                              void* d_out, int out_size)
{
    (void)in_sizes; (void)n_in; (void)out_size;
    const float* input = (const float*)d_in[0];
    const float* h0    = (const float*)d_in[1];
    const float* c0    = (const float*)d_in[2];
    const float* wih   = (const float*)d_in[3];
    const float* whh   = (const float*)d_in[4];
    const float* bih   = (const float*)d_in[5];
    const float* bhh   = (const float*)d_in[6];

    const int xsmem = 2 * STAGES * TILEHALFS * (int)sizeof(__half);
    cudaFuncSetAttribute(xproj_kernel,
                         cudaFuncAttributeMaxDynamicSharedMemorySize, xsmem);
    cudaFuncSetAttribute(lstm_persistent_c0,
                         cudaFuncAttributeMaxDynamicSharedMemorySize, PSMEM);

    prep_kernel<<<1024, 256>>>(input, h0, c0, wih, whh, bih, bhh);
    xproj_kernel<<<dim3(G4 / 64, (T_STEPS * BATCH) / 64), XTHREADS, xsmem>>>();
    lstm_persistent_c0<<<NCTAS, PTHREADS, PSMEM>>>((float*)d_out, c0);
}

// round 12
// speedup vs baseline: 1.0844x; 1.0267x over previous
#include <cuda_runtime.h>
#include <cuda_fp16.h>
#include <cstdint>

#define T_STEPS 256
#define BATCH   64
#define XDIM    512
#define HDIM    2048
#define G4      8192
#define NCTAS   128
#define PTHREADS 512
#define XTHREADS 256
#define KT      64                 // K-tile per stage (halfs) = 128 B rows
#define PSTAGES 6                  // persistent-kernel stages
#define XSTAGES 4                  // xproj stages (power of two)
#define ASTG    8192               // stage tile bytes (64 rows * 128 B)
#define GSTR    68                 // gsum row stride (halfs)
#define GSLAB   (64*GSTR)          // halfs per slab

// persistent smem layout (bytes)
#define OFF_SB   (2*PSTAGES*ASTG)            // 98304  (A: 2 groups * 6 stages)
#define OFF_GSUM (OFF_SB + 2*PSTAGES*ASTG)   // 196608 (B same size)
#define PSMEM    (OFF_GSUM + 4*GSLAB*2)      // + 4 fp16 slabs = 231424 B

// xproj smem layout (bytes)
#define XOFF_SB   (XSTAGES*ASTG)             // 32768
#define XOFF_GSUM (2*XSTAGES*ASTG)           // 65536
#define XSMEM     (XOFF_GSUM + 2*GSLAB*2)    // 82944 B

// ---------------- device scratch ----------------
__device__ __align__(16) __half d_in16 [T_STEPS * BATCH * XDIM];
__device__ __align__(16) __half d_wih16[G4 * XDIM];
__device__ __align__(16) __half d_whh16[G4 * HDIM];
__device__ __align__(16) float  d_bsum [G4];
__device__ __align__(16) __half d_xproj[(size_t)T_STEPS * BATCH * G4];  // fp16
__device__ __align__(16) __half d_h16  [2][BATCH * HDIM];
__device__ __align__(16) float  d_sum  [T_STEPS * BATCH];
__device__ unsigned d_bar;

// ---------------- helpers ----------------
__device__ __forceinline__ void mma16816(float* c,
    uint32_t a0, uint32_t a1, uint32_t a2, uint32_t a3,
    uint32_t b0, uint32_t b1)
{
    asm volatile(
        "mma.sync.aligned.m16n8k16.row.col.f32.f16.f16.f32 "
        "{%0,%1,%2,%3},{%4,%5,%6,%7},{%8,%9},{%0,%1,%2,%3};\n"
        : "+f"(c[0]), "+f"(c[1]), "+f"(c[2]), "+f"(c[3])
        : "r"(a0), "r"(a1), "r"(a2), "r"(a3), "r"(b0), "r"(b1));
}
#define LDSM4(r0, r1, r2, r3, addr) \
    asm volatile("ldmatrix.sync.aligned.m8n8.x4.shared.b16 {%0,%1,%2,%3}, [%4];" \
        : "=r"(r0), "=r"(r1), "=r"(r2), "=r"(r3) : "r"(addr))

__device__ __forceinline__ float tanh_hw(float x) {
    float y;
    asm("tanh.approx.f32 %0, %1;" : "=f"(y) : "f"(x));
    return y;
}
__device__ __forceinline__ float sigmoid_hw(float x) {
    return fmaf(tanh_hw(0.5f * x), 0.5f, 0.5f);
}
__device__ __forceinline__ float exp_hw(float x) {
    float y;
    asm("ex2.approx.ftz.f32 %0, %1;" : "=f"(y) : "f"(x * 1.4426950408889634f));
    return y;
}

__device__ __forceinline__ uint32_t smem_u32(const void* p) {
    return (uint32_t)__cvta_generic_to_shared(p);
}
__device__ __forceinline__ int fperm(int r) { return ((r & 1) << 2) | ((r & 7) >> 1); }

#define CP16(dst_u32, src_ptr) \
    asm volatile("cp.async.cg.shared.global [%0], [%1], 16;\n" :: "r"(dst_u32), "l"(src_ptr))
#define CP_COMMIT() asm volatile("cp.async.commit_group;\n" ::: "memory")
#define CP_WAIT2()  asm volatile("cp.async.wait_group 2;\n" ::: "memory")
#define CP_WAIT4()  asm volatile("cp.async.wait_group 4;\n" ::: "memory")

// row permutation: dst row (CTA-major: cta*64 + gate*16 + jj) -> src gate row
__device__ __forceinline__ int perm_src_row(int r) {
    int cta = r >> 6;
    int ln  = r & 63;
    int gate = ln >> 4;
    int jj   = ln & 15;
    return gate * HDIM + cta * 16 + jj;
}

// ---------------- phase 0 ----------------
__global__ __launch_bounds__(256) void prep_kernel(
    const float* __restrict__ input, const float* __restrict__ h0,
    const float* __restrict__ c0,    const float* __restrict__ wih,
    const float* __restrict__ whh,   const float* __restrict__ bih,
    const float* __restrict__ bhh)
{
    (void)c0;
    const int i0 = blockIdx.x * blockDim.x + threadIdx.x;
    const int stride = gridDim.x * blockDim.x;
    if (i0 == 0) d_bar = 0u;
    for (int i = i0; i < T_STEPS * BATCH * XDIM; i += stride)
        d_in16[i] = __float2half(input[i]);
    for (int i = i0; i < G4 * XDIM; i += stride) {
        int r = i >> 9, k = i & (XDIM - 1);
        d_wih16[i] = __float2half(wih[perm_src_row(r) * XDIM + k]);
    }
    for (int i = i0; i < G4 * HDIM; i += stride) {
        int r = i >> 11, k = i & (HDIM - 1);
        d_whh16[i] = __float2half(whh[(size_t)perm_src_row(r) * HDIM + k]);
    }
    for (int i = i0; i < G4; i += stride) {
        int s = perm_src_row(i);
        d_bsum[i] = bih[s] + bhh[s];
    }
    for (int i = i0; i < BATCH * HDIM; i += stride)
        d_h16[0][i] = __float2half(h0[i]);
    for (int i = i0; i < T_STEPS * BATCH; i += stride)
        d_sum[i] = 0.0f;
}

// ---------------- phase 1: xproj — ldmatrix 2m x 2n x 2k pipeline ----------------
__global__ __launch_bounds__(XTHREADS) void xproj_kernel()
{
    extern __shared__ __align__(1024) char xsmem_raw[];
    const uint32_t sbase = smem_u32(xsmem_raw);
    const uint32_t sA = sbase;
    const uint32_t sB = sbase + XOFF_SB;
    __half* gsum = (__half*)(xsmem_raw + XOFF_GSUM);

    const int tid  = threadIdx.x;
    const int lane = tid & 31;
    const int gwid = tid >> 5;              // 0..7
    const int wm = gwid & 1;                // m half (32 rows)
    const int wn = (gwid >> 1) & 1;         // n half (32 cols)
    const int wk = gwid >> 2;               // k half within stage
    const int n0 = blockIdx.x * 64;
    const int m0 = blockIdx.y * 64;

    // cp.async loader mapping (256 threads fill 8KB A + 8KB B per stage)
    const int lrow = tid >> 2, lch = tid & 3;
    const int fp_s = fperm(lrow);
    const uint32_t d0 = (uint32_t)(lrow * 128 + ((lch ^ fp_s) << 4));
    const uint32_t d1 = (uint32_t)(lrow * 128 + (((lch + 4) ^ fp_s) << 4));
    const int scol = lch * 8;
    const __half* Ag = d_in16  + (size_t)(m0 + lrow) * XDIM + scol;
    const __half* Bg = d_wih16 + (size_t)(n0 + lrow) * XDIM + scol;

    // ldmatrix addressing (identical scheme to persistent kernel)
    const int fp_l = fperm(lane & 7);
    const uint32_t rowA0 = (uint32_t)((wm * 32 + (lane & 15)) * 128);
    const uint32_t rowA1 = rowA0 + 16 * 128;
    const uint32_t rowB0 = (uint32_t)((wn * 32 + ((lane >> 4) & 1) * 8 + (lane & 7)) * 128);
    const uint32_t rowB1 = rowB0 + 16 * 128;
    const int khA = (lane >> 4) & 1;
    const int khB = (lane >> 3) & 1;
    const int kb16 = wk * 2;

    float acc[2][4][4];
    #pragma unroll
    for (int i = 0; i < 2; i++)
        #pragma unroll
        for (int j = 0; j < 4; j++)
            #pragma unroll
            for (int q = 0; q < 4; q++) acc[i][j][q] = 0.0f;

#define XISSUE(SLOT, KB) do {                                                 \
        const uint32_t ao_ = sA + (uint32_t)(SLOT) * ASTG;                    \
        const uint32_t bo_ = sB + (uint32_t)(SLOT) * ASTG;                    \
        CP16(ao_ + d0, Ag + (KB));                                            \
        CP16(ao_ + d1, Ag + (KB) + 32);                                       \
        CP16(bo_ + d0, Bg + (KB));                                            \
        CP16(bo_ + d1, Bg + (KB) + 32);                                       \
        CP_COMMIT();                                                          \
    } while (0)

    #pragma unroll
    for (int st = 0; st < 3; ++st) XISSUE(st, st * KT);

    const int NITX = XDIM / KT;   // 8
    #pragma unroll
    for (int it = 0; it < NITX; ++it) {
        CP_WAIT2();
        __syncthreads();
        const uint32_t At = sA + (uint32_t)((it & 3) * ASTG);
        const uint32_t Bt = sB + (uint32_t)((it & 3) * ASTG);
        #pragma unroll
        for (int kc = 0; kc < 2; ++kc) {
            const uint32_t ccA = (uint32_t)((((kb16 + kc) << 1) | khA) ^ fp_l) << 4;
            const uint32_t ccB = (uint32_t)((((kb16 + kc) << 1) | khB) ^ fp_l) << 4;
            uint32_t a0[4], a1[4], bb0[4], bb1[4];
            LDSM4(a0[0], a0[1], a0[2], a0[3], At + rowA0 + ccA);
            LDSM4(a1[0], a1[1], a1[2], a1[3], At + rowA1 + ccA);
            LDSM4(bb0[0], bb0[1], bb0[2], bb0[3], Bt + rowB0 + ccB);
            LDSM4(bb1[0], bb1[1], bb1[2], bb1[3], Bt + rowB1 + ccB);
            mma16816(acc[0][0], a0[0], a0[1], a0[2], a0[3], bb0[0], bb0[1]);
            mma16816(acc[0][1], a0[0], a0[1], a0[2], a0[3], bb0[2], bb0[3]);
            mma16816(acc[0][2], a0[0], a0[1], a0[2], a0[3], bb1[0], bb1[1]);
            mma16816(acc[0][3], a0[0], a0[1], a0[2], a0[3], bb1[2], bb1[3]);
            mma16816(acc[1][0], a1[0], a1[1], a1[2], a1[3], bb0[0], bb0[1]);
            mma16816(acc[1][1], a1[0], a1[1], a1[2], a1[3], bb0[2], bb0[3]);
            mma16816(acc[1][2], a1[0], a1[1], a1[2], a1[3], bb1[0], bb1[1]);
            mma16816(acc[1][3], a1[0], a1[1], a1[2], a1[3], bb1[2], bb1[3]);
        }
        __syncthreads();
        if (it + 3 < NITX) {
            XISSUE((it + 3) & 3, (it + 3) * KT);
        } else {
            CP_COMMIT();
        }
    }
#undef XISSUE

    // slab write (fp16): slab = wk
    {
        __half* gs = gsum + (size_t)wk * GSLAB;
        #pragma unroll
        for (int mf = 0; mf < 2; ++mf) {
            const int row = wm * 32 + mf * 16 + (lane >> 2);
            #pragma unroll
            for (int nf = 0; nf < 4; ++nf) {
                const int col = wn * 32 + nf * 8 + (lane & 3) * 2;
                *(__half2*)&gs[row * GSTR + col] =
                    __floats2half2_rn(acc[mf][nf][0], acc[mf][nf][1]);
                *(__half2*)&gs[(row + 8) * GSTR + col] =
                    __floats2half2_rn(acc[mf][nf][2], acc[mf][nf][3]);
            }
        }
    }
    __syncthreads();

    // reduce 2 slabs + bias, store fp16: thread -> row=tid>>2, 16 cols
    {
        const int r  = tid >> 2;
        const int c0 = (tid & 3) * 16;
        const __half* g0 = gsum + (size_t)r * GSTR + c0;
        const __half* g1 = g0 + GSLAB;
        __half* dst = d_xproj + (size_t)(m0 + r) * G4 + n0 + c0;
        const float* bs = d_bsum + n0 + c0;
        #pragma unroll
        for (int j = 0; j < 8; ++j) {
            float2 v0 = __half22float2(*(const __half2*)(g0 + 2 * j));
            float2 v1 = __half22float2(*(const __half2*)(g1 + 2 * j));
            float2 bb = *(const float2*)(bs + 2 * j);
            *(__half2*)(dst + 2 * j) =
                __floats2half2_rn(v0.x + v1.x + bb.x, v0.y + v1.y + bb.y);
        }
    }
}

// ---------------- grid barrier (128 CTAs co-resident) ----------------
__device__ __forceinline__ void grid_barrier(unsigned target)
{
    __syncthreads();
    if (threadIdx.x == 0) {
        __threadfence();
        atomicAdd(&d_bar, 1u);
        volatile unsigned* p = &d_bar;
        while (*p < target) { }
        __threadfence();
    }
    __syncthreads();
}

// ---------------- phase 2: persistent recurrent kernel (identical to R11) ----
__global__ __launch_bounds__(PTHREADS, 1) void lstm_persistent_c0(
    float* __restrict__ out, const float* __restrict__ c0)
{
    extern __shared__ __align__(1024) char smem_raw[];
    const uint32_t sbase = smem_u32(smem_raw);
    __half* gsum = (__half*)(smem_raw + OFF_GSUM);

    const int cta  = blockIdx.x;
    const int tid  = threadIdx.x;
    const int lane = tid & 31;
    const int g    = tid >> 8;              // K-half group (0,1)
    const int gtid = tid & 255;
    const int gwid = gtid >> 5;             // warp in group 0..7
    const int wm = gwid & 1;                // m half (batch 32)
    const int wn = (gwid >> 1) & 1;         // n half (gate 32)
    const int wk = gwid >> 2;               // k quarter within group
    const int gq = lane >> 2, tq = lane & 3;
    const int n0 = cta * 64;                // permuted gate-row base
    const int KOFF = g * (HDIM / 2);
    const int NIT  = (HDIM / 2) / KT;       // 16

    const uint32_t aGrp = sbase + (uint32_t)g * PSTAGES * ASTG;
    const uint32_t bGrp = sbase + OFF_SB + (uint32_t)g * PSTAGES * ASTG;

    const int lrow = gtid >> 2, lch = gtid & 3;
    const int fp_s = fperm(lrow);
    const uint32_t d0 = (uint32_t)(lrow * 128 + ((lch ^ fp_s) << 4));
    const uint32_t d1 = (uint32_t)(lrow * 128 + (((lch + 4) ^ fp_s) << 4));
    const int scol = lch * 8;
    const __half* Bg = d_whh16 + (size_t)(n0 + lrow) * HDIM + KOFF + scol;

    const int fp_l = fperm(lane & 7);
    const uint32_t rowA0 = (uint32_t)((wm * 32 + (lane & 15)) * 128);
    const uint32_t rowA1 = rowA0 + 16 * 128;
    const uint32_t rowB0 = (uint32_t)((wn * 32 + ((lane >> 4) & 1) * 8 + (lane & 7)) * 128);
    const uint32_t rowB1 = rowB0 + 16 * 128;
    const int khA = (lane >> 4) & 1;
    const int khB = (lane >> 3) & 1;
    const int kb16 = wk * 2;

    const size_t HOFF = (size_t)T_STEPS * BATCH * HDIM;
    const size_t COFF = HOFF + (size_t)BATCH * HDIM;

    const int b1 = tid >> 4,        jj1 = tid & 15;
    const int b2 = 32 + (tid >> 4), jj2 = jj1;
    float creg1 = c0[b1 * HDIM + cta * 16 + jj1];
    float creg2 = c0[b2 * HDIM + cta * 16 + jj2];

    float pe1 = 0.0f, pe2 = 0.0f;

    unsigned bar_target = 0;

#define ISSUE(SLOT, KB, HB) do {                                              \
        const __half* asrc_ = (HB) + (size_t)lrow * HDIM + KOFF + (KB) + scol;\
        const __half* bsrc_ = Bg + (KB);                                      \
        const uint32_t ao_ = aGrp + (uint32_t)(SLOT) * ASTG;                  \
        const uint32_t bo_ = bGrp + (uint32_t)(SLOT) * ASTG;                  \
        CP16(ao_ + d0, asrc_);                                                \
        CP16(ao_ + d1, asrc_ + 32);                                           \
        CP16(bo_ + d0, bsrc_);                                                \
        CP16(bo_ + d1, bsrc_ + 32);                                           \
        CP_COMMIT();                                                          \
    } while (0)

    {
        const __half* hbuf = d_h16[0];
        #pragma unroll
        for (int st = 0; st < 5; ++st) ISSUE(st, st * KT, hbuf);
    }

    #pragma unroll 1
    for (int t = 0; t < T_STEPS; ++t) {
        const __half* hbuf = d_h16[t & 1];

        const __half* xp = d_xproj + (size_t)t * BATCH * G4 + n0;
        const __half* xr1 = xp + (size_t)b1 * G4;
        const __half* xr2 = xp + (size_t)b2 * G4;
        float xv1[4], xv2[4];
        #pragma unroll
        for (int q = 0; q < 4; ++q) {
            xv1[q] = __half2float(xr1[q * 16 + jj1]);
            xv2[q] = __half2float(xr2[q * 16 + jj2]);
        }

        float acc[2][4][4];
        #pragma unroll
        for (int i = 0; i < 2; i++)
            #pragma unroll
            for (int j = 0; j < 4; j++)
                #pragma unroll
                for (int q = 0; q < 4; q++) acc[i][j][q] = 0.0f;

        #pragma unroll
        for (int it = 0; it < NIT; ++it) {
            const int slot = it % PSTAGES;          // const-folded
            CP_WAIT4();
            asm volatile("bar.sync %0, 256;\n" :: "r"(g + 1) : "memory");
            const uint32_t At = aGrp + (uint32_t)(slot * ASTG);
            const uint32_t Bt = bGrp + (uint32_t)(slot * ASTG);
            #pragma unroll
            for (int kc = 0; kc < 2; ++kc) {
                const uint32_t ccA = (uint32_t)((((kb16 + kc) << 1) | khA) ^ fp_l) << 4;
                const uint32_t ccB = (uint32_t)((((kb16 + kc) << 1) | khB) ^ fp_l) << 4;
                uint32_t a0[4], a1[4], bb0[4], bb1[4];
                LDSM4(a0[0], a0[1], a0[2], a0[3], At + rowA0 + ccA);
                LDSM4(a1[0], a1[1], a1[2], a1[3], At + rowA1 + ccA);
                LDSM4(bb0[0], bb0[1], bb0[2], bb0[3], Bt + rowB0 + ccB);
                LDSM4(bb1[0], bb1[1], bb1[2], bb1[3], Bt + rowB1 + ccB);
                mma16816(acc[0][0], a0[0], a0[1], a0[2], a0[3], bb0[0], bb0[1]);
                mma16816(acc[0][1], a0[0], a0[1], a0[2], a0[3], bb0[2], bb0[3]);
                mma16816(acc[0][2], a0[0], a0[1], a0[2], a0[3], bb1[0], bb1[1]);
                mma16816(acc[0][3], a0[0], a0[1], a0[2], a0[3], bb1[2], bb1[3]);
                mma16816(acc[1][0], a1[0], a1[1], a1[2], a1[3], bb0[0], bb0[1]);
                mma16816(acc[1][1], a1[0], a1[1], a1[2], a1[3], bb0[2], bb0[3]);
                mma16816(acc[1][2], a1[0], a1[1], a1[2], a1[3], bb1[0], bb1[1]);
                mma16816(acc[1][3], a1[0], a1[1], a1[2], a1[3], bb1[2], bb1[3]);
            }
            if (it + 5 < NIT) {
                const int wslot = (it + 5) % PSTAGES;   // const-folded
                ISSUE(wslot, (it + 5) * KT, hbuf);
            } else {
                CP_COMMIT();
            }
        }

        {
            __half* gs = gsum + (size_t)(g * 2 + wk) * GSLAB;
            #pragma unroll
            for (int mf = 0; mf < 2; ++mf) {
                const int row = wm * 32 + mf * 16 + gq;
                #pragma unroll
                for (int nf = 0; nf < 4; ++nf) {
                    const int col = wn * 32 + nf * 8 + tq * 2;
                    *(__half2*)&gs[row * GSTR + col] =
                        __floats2half2_rn(acc[mf][nf][0], acc[mf][nf][1]);
                    *(__half2*)&gs[(row + 8) * GSTR + col] =
                        __floats2half2_rn(acc[mf][nf][2], acc[mf][nf][3]);
                }
            }
        }
        __syncthreads();

        __half* hN = d_h16[(t + 1) & 1];
        float e1, e2;
        {
            const __half* gb = gsum + (size_t)b1 * GSTR;
            float ip = __half2float(gb[jj1]) + __half2float(gb[GSLAB + jj1])
                     + __half2float(gb[2*GSLAB + jj1]) + __half2float(gb[3*GSLAB + jj1]) + xv1[0];
            float fpv= __half2float(gb[16+jj1]) + __half2float(gb[GSLAB+16+jj1])
                     + __half2float(gb[2*GSLAB+16+jj1]) + __half2float(gb[3*GSLAB+16+jj1]) + xv1[1];
            float gp = __half2float(gb[32+jj1]) + __half2float(gb[GSLAB+32+jj1])
                     + __half2float(gb[2*GSLAB+32+jj1]) + __half2float(gb[3*GSLAB+32+jj1]) + xv1[2];
            float op = __half2float(gb[48+jj1]) + __half2float(gb[GSLAB+48+jj1])
                     + __half2float(gb[2*GSLAB+48+jj1]) + __half2float(gb[3*GSLAB+48+jj1]) + xv1[3];
            float ii = sigmoid_hw(ip), ff = sigmoid_hw(fpv);
            float gg = tanh_hw(gp),    oo = sigmoid_hw(op);
            float cn = ff * creg1 + ii * gg;
            creg1 = cn;
            float hn = oo * tanh_hw(cn);
            hN[b1 * HDIM + cta * 16 + jj1] = __float2half(hn);
            if (t == T_STEPS - 1) {
                out[HOFF + (size_t)b1 * HDIM + cta * 16 + jj1] = hn;
                out[COFF + (size_t)b1 * HDIM + cta * 16 + jj1] = cn;
            }
            e1 = exp_hw(hn);
        }
        {
            const __half* gb = gsum + (size_t)b2 * GSTR;
            float ip = __half2float(gb[jj2]) + __half2float(gb[GSLAB + jj2])
                     + __half2float(gb[2*GSLAB + jj2]) + __half2float(gb[3*GSLAB + jj2]) + xv2[0];
            float fpv= __half2float(gb[16+jj2]) + __half2float(gb[GSLAB+16+jj2])
                     + __half2float(gb[2*GSLAB+16+jj2]) + __half2float(gb[3*GSLAB+16+jj2]) + xv2[1];
            float gp = __half2float(gb[32+jj2]) + __half2float(gb[GSLAB+32+jj2])
                     + __half2float(gb[2*GSLAB+32+jj2]) + __half2float(gb[3*GSLAB+32+jj2]) + xv2[2];
            float op = __half2float(gb[48+jj2]) + __half2float(gb[GSLAB+48+jj2])
                     + __half2float(gb[2*GSLAB+48+jj2]) + __half2float(gb[3*GSLAB+48+jj2]) + xv2[3];
            float ii = sigmoid_hw(ip), ff = sigmoid_hw(fpv);
            float gg = tanh_hw(gp),    oo = sigmoid_hw(op);
            float cn = ff * creg2 + ii * gg;
            creg2 = cn;
            float hn = oo * tanh_hw(cn);
            hN[b2 * HDIM + cta * 16 + jj2] = __float2half(hn);
            if (t == T_STEPS - 1) {
                out[HOFF + (size_t)b2 * HDIM + cta * 16 + jj2] = hn;
                out[COFF + (size_t)b2 * HDIM + cta * 16 + jj2] = cn;
            }
            e2 = exp_hw(hn);
        }
        float v1 = e1, v2 = e2;
        #pragma unroll
        for (int o = 8; o > 0; o >>= 1) {
            v1 += __shfl_xor_sync(0xffffffffu, v1, o);
            v2 += __shfl_xor_sync(0xffffffffu, v2, o);
        }

        bar_target += NCTAS;
        grid_barrier(bar_target);

        if (t + 1 < T_STEPS) {
            const __half* hnext = d_h16[(t + 1) & 1];
            #pragma unroll
            for (int st = 0; st < 5; ++st) ISSUE(st, st * KT, hnext);
        }
        if (t > 0) {
            float s1 = __ldcg(&d_sum[(t - 1) * BATCH + b1]);
            float s2 = __ldcg(&d_sum[(t - 1) * BATCH + b2]);
            out[(size_t)(t - 1) * BATCH * HDIM + (size_t)b1 * HDIM + cta * 16 + jj1] = pe1 * (1.0f / s1);
            out[(size_t)(t - 1) * BATCH * HDIM + (size_t)b2 * HDIM + cta * 16 + jj2] = pe2 * (1.0f / s2);
        }
        if ((lane & 15) == 0) {
            atomicAdd(&d_sum[t * BATCH + b1], v1);
            atomicAdd(&d_sum[t * BATCH + b2], v2);
        }
        pe1 = e1;
        pe2 = e2;
    }

    bar_target += NCTAS;
    grid_barrier(bar_target);
    {
        float s1 = __ldcg(&d_sum[(T_STEPS - 1) * BATCH + b1]);
        float s2 = __ldcg(&d_sum[(T_STEPS - 1) * BATCH + b2]);
        out[(size_t)(T_STEPS - 1) * BATCH * HDIM + (size_t)b1 * HDIM + cta * 16 + jj1] = pe1 * (1.0f / s1);
        out[(size_t)(T_STEPS - 1) * BATCH * HDIM + (size_t)b2 * HDIM + cta * 16 + jj2] = pe2 * (1.0f / s2);
    }
#undef ISSUE
}

// ---------------- entry ----------------
extern "C" void kernel_launch(void* const* d_in, const int* in_sizes, int n_in,
                              void* d_out, int out_size)
{
    (void)in_sizes; (void)n_in; (void)out_size;
    const float* input = (const float*)d_in[0];
    const float* h0    = (const float*)d_in[1];
    const float* c0    = (const float*)d_in[2];
    const float* wih   = (const float*)d_in[3];
    const float* whh   = (const float*)d_in[4];
    const float* bih   = (const float*)d_in[5];
    const float* bhh   = (const float*)d_in[6];

    cudaFuncSetAttribute(xproj_kernel,
                         cudaFuncAttributeMaxDynamicSharedMemorySize, XSMEM);
    cudaFuncSetAttribute(lstm_persistent_c0,
                         cudaFuncAttributeMaxDynamicSharedMemorySize, PSMEM);

    prep_kernel<<<1024, 256>>>(input, h0, c0, wih, whh, bih, bhh);
    xproj_kernel<<<dim3(G4 / 64, (T_STEPS * BATCH) / 64), XTHREADS, XSMEM>>>();
    lstm_persistent_c0<<<NCTAS, PTHREADS, PSMEM>>>((float*)d_out, c0);
}

// round 13
// speedup vs baseline: 1.0916x; 1.0066x over previous
#include <cuda_runtime.h>
#include <cuda_fp16.h>
#include <cstdint>

#define T_STEPS 256
#define BATCH   64
#define XDIM    512
#define HDIM    2048
#define G4      8192
#define NCTAS   128
#define PTHREADS 512
#define KT      64                 // K-tile per stage (halfs) = 128 B rows
#define PSTAGES 6                  // persistent-kernel stages
#define ASTG    8192               // persistent stage tile bytes (64 rows * 128 B)
#define GSTR    68                 // persistent gsum row stride (halfs)
#define GSLAB   (64*GSTR)          // halfs per slab

// persistent smem layout (bytes)
#define OFF_SB   (2*PSTAGES*ASTG)            // 98304
#define OFF_GSUM (OFF_SB + 2*PSTAGES*ASTG)   // 196608
#define PSMEM    (OFF_GSUM + 4*GSLAB*2)      // 231424 B

// xproj v2: 128x128 tiles, 512 threads
#define X2THREADS 512
#define XNST    4                  // stages
#define XASTG   16384              // A stage: 128 rows * 128 B
#define XGSTR   132                // gsum stride (halfs)
#define XGSLAB  (128*XGSTR)
#define X2OFF_B (XNST*XASTG)       // 65536
#define X2OFF_G (2*XNST*XASTG)     // 131072
#define X2SMEM  (X2OFF_G + 2*XGSLAB*2)   // 198656 B

// ---------------- device scratch ----------------
__device__ __align__(16) __half d_in16 [T_STEPS * BATCH * XDIM];
__device__ __align__(16) __half d_wih16[G4 * XDIM];
__device__ __align__(16) __half d_whh16[G4 * HDIM];
__device__ __align__(16) float  d_bsum [G4];
__device__ __align__(16) __half d_xproj[(size_t)T_STEPS * BATCH * G4];  // fp16
__device__ __align__(16) __half d_h16  [2][BATCH * HDIM];
__device__ __align__(16) float  d_sum  [T_STEPS * BATCH];
__device__ unsigned d_bar;

// ---------------- helpers ----------------
__device__ __forceinline__ void mma16816(float* c,
    uint32_t a0, uint32_t a1, uint32_t a2, uint32_t a3,
    uint32_t b0, uint32_t b1)
{
    asm volatile(
        "mma.sync.aligned.m16n8k16.row.col.f32.f16.f16.f32 "
        "{%0,%1,%2,%3},{%4,%5,%6,%7},{%8,%9},{%0,%1,%2,%3};\n"
        : "+f"(c[0]), "+f"(c[1]), "+f"(c[2]), "+f"(c[3])
        : "r"(a0), "r"(a1), "r"(a2), "r"(a3), "r"(b0), "r"(b1));
}
#define LDSM4(r0, r1, r2, r3, addr) \
    asm volatile("ldmatrix.sync.aligned.m8n8.x4.shared.b16 {%0,%1,%2,%3}, [%4];" \
        : "=r"(r0), "=r"(r1), "=r"(r2), "=r"(r3) : "r"(addr))

__device__ __forceinline__ float tanh_hw(float x) {
    float y;
    asm("tanh.approx.f32 %0, %1;" : "=f"(y) : "f"(x));
    return y;
}
__device__ __forceinline__ float sigmoid_hw(float x) {
    return fmaf(tanh_hw(0.5f * x), 0.5f, 0.5f);
}
__device__ __forceinline__ float exp_hw(float x) {
    float y;
    asm("ex2.approx.ftz.f32 %0, %1;" : "=f"(y) : "f"(x * 1.4426950408889634f));
    return y;
}

__device__ __forceinline__ uint32_t smem_u32(const void* p) {
    return (uint32_t)__cvta_generic_to_shared(p);
}
__device__ __forceinline__ int fperm(int r) { return ((r & 1) << 2) | ((r & 7) >> 1); }

#define CP16(dst_u32, src_ptr) \
    asm volatile("cp.async.cg.shared.global [%0], [%1], 16;\n" :: "r"(dst_u32), "l"(src_ptr))
#define CP_COMMIT() asm volatile("cp.async.commit_group;\n" ::: "memory")
#define CP_WAIT2()  asm volatile("cp.async.wait_group 2;\n" ::: "memory")
#define CP_WAIT4()  asm volatile("cp.async.wait_group 4;\n" ::: "memory")

// row permutation: dst row (CTA-major: cta*64 + gate*16 + jj) -> src gate row
__device__ __forceinline__ int perm_src_row(int r) {
    int cta = r >> 6;
    int ln  = r & 63;
    int gate = ln >> 4;
    int jj   = ln & 15;
    return gate * HDIM + cta * 16 + jj;
}

// ---------------- phase 0 ----------------
__global__ __launch_bounds__(256) void prep_kernel(
    const float* __restrict__ input, const float* __restrict__ h0,
    const float* __restrict__ c0,    const float* __restrict__ wih,
    const float* __restrict__ whh,   const float* __restrict__ bih,
    const float* __restrict__ bhh)
{
    (void)c0;
    const int i0 = blockIdx.x * blockDim.x + threadIdx.x;
    const int stride = gridDim.x * blockDim.x;
    if (i0 == 0) d_bar = 0u;
    for (int i = i0; i < T_STEPS * BATCH * XDIM; i += stride)
        d_in16[i] = __float2half(input[i]);
    for (int i = i0; i < G4 * XDIM; i += stride) {
        int r = i >> 9, k = i & (XDIM - 1);
        d_wih16[i] = __float2half(wih[perm_src_row(r) * XDIM + k]);
    }
    for (int i = i0; i < G4 * HDIM; i += stride) {
        int r = i >> 11, k = i & (HDIM - 1);
        d_whh16[i] = __float2half(whh[(size_t)perm_src_row(r) * HDIM + k]);
    }
    for (int i = i0; i < G4; i += stride) {
        int s = perm_src_row(i);
        d_bsum[i] = bih[s] + bhh[s];
    }
    for (int i = i0; i < BATCH * HDIM; i += stride)
        d_h16[0][i] = __float2half(h0[i]);
    for (int i = i0; i < T_STEPS * BATCH; i += stride)
        d_sum[i] = 0.0f;
}

// ---------------- phase 1: xproj v2 — 128x128 tiles, m2 x n4 x k2 ----------------
__global__ __launch_bounds__(X2THREADS) void xproj_kernel()
{
    extern __shared__ __align__(1024) char xsmem_raw[];
    const uint32_t sbase = smem_u32(xsmem_raw);
    const uint32_t sA = sbase;
    const uint32_t sB = sbase + X2OFF_B;
    __half* gsum = (__half*)(xsmem_raw + X2OFF_G);

    const int tid  = threadIdx.x;
    const int lane = tid & 31;
    const int gwid = tid >> 5;              // 0..15
    const int wm = gwid & 1;                // m half (64 rows)
    const int wn = (gwid >> 1) & 3;         // n quarter (32 cols)
    const int wk = gwid >> 3;               // k half within stage
    const int n0 = blockIdx.x * 128;
    const int m0 = blockIdx.y * 128;

    // cp.async loader: 512 threads fill 16KB A + 16KB B per stage (4 cp16 each)
    const int lrow = tid >> 2, lch = tid & 3;      // 128 rows, 4 chunk slots
    const int fp_s = fperm(lrow);
    const uint32_t d0 = (uint32_t)(lrow * 128 + ((lch ^ fp_s) << 4));
    const uint32_t d1 = (uint32_t)(lrow * 128 + (((lch + 4) ^ fp_s) << 4));
    const int scol = lch * 8;
    const __half* Ag = d_in16  + (size_t)(m0 + lrow) * XDIM + scol;
    const __half* Bg = d_wih16 + (size_t)(n0 + lrow) * XDIM + scol;

    // ldmatrix addressing
    const int fp_l = fperm(lane & 7);
    uint32_t rowA[4];
    #pragma unroll
    for (int mf = 0; mf < 4; ++mf)
        rowA[mf] = (uint32_t)((wm * 64 + mf * 16 + (lane & 15)) * 128);
    const uint32_t rowB0 = (uint32_t)((wn * 32 + ((lane >> 4) & 1) * 8 + (lane & 7)) * 128);
    const uint32_t rowB1 = rowB0 + 16 * 128;
    const int khA = (lane >> 4) & 1;
    const int khB = (lane >> 3) & 1;
    const int kb16 = wk * 2;

    float acc[4][4][4];   // [mf][nf][reg]
    #pragma unroll
    for (int i = 0; i < 4; i++)
        #pragma unroll
        for (int j = 0; j < 4; j++)
            #pragma unroll
            for (int q = 0; q < 4; q++) acc[i][j][q] = 0.0f;

#define XISSUE(SLOT, KB) do {                                                 \
        const uint32_t ao_ = sA + (uint32_t)(SLOT) * XASTG;                   \
        const uint32_t bo_ = sB + (uint32_t)(SLOT) * XASTG;                   \
        CP16(ao_ + d0, Ag + (KB));                                            \
        CP16(ao_ + d1, Ag + (KB) + 32);                                       \
        CP16(bo_ + d0, Bg + (KB));                                            \
        CP16(bo_ + d1, Bg + (KB) + 32);                                       \
        CP_COMMIT();                                                          \
    } while (0)

    #pragma unroll
    for (int st = 0; st < 3; ++st) XISSUE(st, st * KT);

    const int NITX = XDIM / KT;   // 8
    #pragma unroll
    for (int it = 0; it < NITX; ++it) {
        CP_WAIT2();
        __syncthreads();
        const uint32_t At = sA + (uint32_t)((it & 3) * XASTG);
        const uint32_t Bt = sB + (uint32_t)((it & 3) * XASTG);
        #pragma unroll
        for (int kc = 0; kc < 2; ++kc) {
            const uint32_t ccA = (uint32_t)((((kb16 + kc) << 1) | khA) ^ fp_l) << 4;
            const uint32_t ccB = (uint32_t)((((kb16 + kc) << 1) | khB) ^ fp_l) << 4;
            uint32_t a[4][4], bb0[4], bb1[4];
            #pragma unroll
            for (int mf = 0; mf < 4; ++mf)
                LDSM4(a[mf][0], a[mf][1], a[mf][2], a[mf][3], At + rowA[mf] + ccA);
            LDSM4(bb0[0], bb0[1], bb0[2], bb0[3], Bt + rowB0 + ccB);
            LDSM4(bb1[0], bb1[1], bb1[2], bb1[3], Bt + rowB1 + ccB);
            #pragma unroll
            for (int mf = 0; mf < 4; ++mf) {
                mma16816(acc[mf][0], a[mf][0], a[mf][1], a[mf][2], a[mf][3], bb0[0], bb0[1]);
                mma16816(acc[mf][1], a[mf][0], a[mf][1], a[mf][2], a[mf][3], bb0[2], bb0[3]);
                mma16816(acc[mf][2], a[mf][0], a[mf][1], a[mf][2], a[mf][3], bb1[0], bb1[1]);
                mma16816(acc[mf][3], a[mf][0], a[mf][1], a[mf][2], a[mf][3], bb1[2], bb1[3]);
            }
        }
        __syncthreads();
        if (it + 3 < NITX) {
            XISSUE((it + 3) & 3, (it + 3) * KT);
        } else {
            CP_COMMIT();
        }
    }
#undef XISSUE

    // slab write (fp16): slab = wk (2 slabs of 128x128)
    {
        __half* gs = gsum + (size_t)wk * XGSLAB;
        const int gq = lane >> 2, tq = lane & 3;
        #pragma unroll
        for (int mf = 0; mf < 4; ++mf) {
            const int row = wm * 64 + mf * 16 + gq;
            #pragma unroll
            for (int nf = 0; nf < 4; ++nf) {
                const int col = wn * 32 + nf * 8 + tq * 2;
                *(__half2*)&gs[row * XGSTR + col] =
                    __floats2half2_rn(acc[mf][nf][0], acc[mf][nf][1]);
                *(__half2*)&gs[(row + 8) * XGSTR + col] =
                    __floats2half2_rn(acc[mf][nf][2], acc[mf][nf][3]);
            }
        }
    }
    __syncthreads();

    // reduce 2 slabs + bias, store fp16: thread -> row=tid>>2, 32 cols
    {
        const int r  = tid >> 2;
        const int c0 = (tid & 3) * 32;
        const __half* g0 = gsum + (size_t)r * XGSTR + c0;
        const __half* g1 = g0 + XGSLAB;
        __half* dst = d_xproj + (size_t)(m0 + r) * G4 + n0 + c0;
        const float* bs = d_bsum + n0 + c0;
        #pragma unroll
        for (int j = 0; j < 16; ++j) {
            float2 v0 = __half22float2(*(const __half2*)(g0 + 2 * j));
            float2 v1 = __half22float2(*(const __half2*)(g1 + 2 * j));
            float2 bb = *(const float2*)(bs + 2 * j);
            *(__half2*)(dst + 2 * j) =
                __floats2half2_rn(v0.x + v1.x + bb.x, v0.y + v1.y + bb.y);
        }
    }
}

// ---------------- grid barrier (128 CTAs co-resident) ----------------
__device__ __forceinline__ void grid_barrier(unsigned target)
{
    __syncthreads();
    if (threadIdx.x == 0) {
        __threadfence();
        atomicAdd(&d_bar, 1u);
        volatile unsigned* p = &d_bar;
        while (*p < target) { }
        __threadfence();
    }
    __syncthreads();
}

// ---------------- phase 2: persistent recurrent kernel (identical to R12) ----
__global__ __launch_bounds__(PTHREADS, 1) void lstm_persistent_c0(
    float* __restrict__ out, const float* __restrict__ c0)
{
    extern __shared__ __align__(1024) char smem_raw[];
    const uint32_t sbase = smem_u32(smem_raw);
    __half* gsum = (__half*)(smem_raw + OFF_GSUM);

    const int cta  = blockIdx.x;
    const int tid  = threadIdx.x;
    const int lane = tid & 31;
    const int g    = tid >> 8;
    const int gtid = tid & 255;
    const int gwid = gtid >> 5;
    const int wm = gwid & 1;
    const int wn = (gwid >> 1) & 1;
    const int wk = gwid >> 2;
    const int gq = lane >> 2, tq = lane & 3;
    const int n0 = cta * 64;
    const int KOFF = g * (HDIM / 2);
    const int NIT  = (HDIM / 2) / KT;

    const uint32_t aGrp = sbase + (uint32_t)g * PSTAGES * ASTG;
    const uint32_t bGrp = sbase + OFF_SB + (uint32_t)g * PSTAGES * ASTG;

    const int lrow = gtid >> 2, lch = gtid & 3;
    const int fp_s = fperm(lrow);
    const uint32_t d0 = (uint32_t)(lrow * 128 + ((lch ^ fp_s) << 4));
    const uint32_t d1 = (uint32_t)(lrow * 128 + (((lch + 4) ^ fp_s) << 4));
    const int scol = lch * 8;
    const __half* Bg = d_whh16 + (size_t)(n0 + lrow) * HDIM + KOFF + scol;

    const int fp_l = fperm(lane & 7);
    const uint32_t rowA0 = (uint32_t)((wm * 32 + (lane & 15)) * 128);
    const uint32_t rowA1 = rowA0 + 16 * 128;
    const uint32_t rowB0 = (uint32_t)((wn * 32 + ((lane >> 4) & 1) * 8 + (lane & 7)) * 128);
    const uint32_t rowB1 = rowB0 + 16 * 128;
    const int khA = (lane >> 4) & 1;
    const int khB = (lane >> 3) & 1;
    const int kb16 = wk * 2;

    const size_t HOFF = (size_t)T_STEPS * BATCH * HDIM;
    const size_t COFF = HOFF + (size_t)BATCH * HDIM;

    const int b1 = tid >> 4,        jj1 = tid & 15;
    const int b2 = 32 + (tid >> 4), jj2 = jj1;
    float creg1 = c0[b1 * HDIM + cta * 16 + jj1];
    float creg2 = c0[b2 * HDIM + cta * 16 + jj2];

    float pe1 = 0.0f, pe2 = 0.0f;

    unsigned bar_target = 0;

#define ISSUE(SLOT, KB, HB) do {                                              \
        const __half* asrc_ = (HB) + (size_t)lrow * HDIM + KOFF + (KB) + scol;\
        const __half* bsrc_ = Bg + (KB);                                      \
        const uint32_t ao_ = aGrp + (uint32_t)(SLOT) * ASTG;                  \
        const uint32_t bo_ = bGrp + (uint32_t)(SLOT) * ASTG;                  \
        CP16(ao_ + d0, asrc_);                                                \
        CP16(ao_ + d1, asrc_ + 32);                                           \
        CP16(bo_ + d0, bsrc_);                                                \
        CP16(bo_ + d1, bsrc_ + 32);                                           \
        CP_COMMIT();                                                          \
    } while (0)

    {
        const __half* hbuf = d_h16[0];
        #pragma unroll
        for (int st = 0; st < 5; ++st) ISSUE(st, st * KT, hbuf);
    }

    #pragma unroll 1
    for (int t = 0; t < T_STEPS; ++t) {
        const __half* hbuf = d_h16[t & 1];

        const __half* xp = d_xproj + (size_t)t * BATCH * G4 + n0;
        const __half* xr1 = xp + (size_t)b1 * G4;
        const __half* xr2 = xp + (size_t)b2 * G4;
        float xv1[4], xv2[4];
        #pragma unroll
        for (int q = 0; q < 4; ++q) {
            xv1[q] = __half2float(xr1[q * 16 + jj1]);
            xv2[q] = __half2float(xr2[q * 16 + jj2]);
        }

        float acc[2][4][4];
        #pragma unroll
        for (int i = 0; i < 2; i++)
            #pragma unroll
            for (int j = 0; j < 4; j++)
                #pragma unroll
                for (int q = 0; q < 4; q++) acc[i][j][q] = 0.0f;

        #pragma unroll
        for (int it = 0; it < NIT; ++it) {
            const int slot = it % PSTAGES;          // const-folded
            CP_WAIT4();
            asm volatile("bar.sync %0, 256;\n" :: "r"(g + 1) : "memory");
            const uint32_t At = aGrp + (uint32_t)(slot * ASTG);
            const uint32_t Bt = bGrp + (uint32_t)(slot * ASTG);
            #pragma unroll
            for (int kc = 0; kc < 2; ++kc) {
                const uint32_t ccA = (uint32_t)((((kb16 + kc) << 1) | khA) ^ fp_l) << 4;
                const uint32_t ccB = (uint32_t)((((kb16 + kc) << 1) | khB) ^ fp_l) << 4;
                uint32_t a0[4], a1[4], bb0[4], bb1[4];
                LDSM4(a0[0], a0[1], a0[2], a0[3], At + rowA0 + ccA);
                LDSM4(a1[0], a1[1], a1[2], a1[3], At + rowA1 + ccA);
                LDSM4(bb0[0], bb0[1], bb0[2], bb0[3], Bt + rowB0 + ccB);
                LDSM4(bb1[0], bb1[1], bb1[2], bb1[3], Bt + rowB1 + ccB);
                mma16816(acc[0][0], a0[0], a0[1], a0[2], a0[3], bb0[0], bb0[1]);
                mma16816(acc[0][1], a0[0], a0[1], a0[2], a0[3], bb0[2], bb0[3]);
                mma16816(acc[0][2], a0[0], a0[1], a0[2], a0[3], bb1[0], bb1[1]);
                mma16816(acc[0][3], a0[0], a0[1], a0[2], a0[3], bb1[2], bb1[3]);
                mma16816(acc[1][0], a1[0], a1[1], a1[2], a1[3], bb0[0], bb0[1]);
                mma16816(acc[1][1], a1[0], a1[1], a1[2], a1[3], bb0[2], bb0[3]);
                mma16816(acc[1][2], a1[0], a1[1], a1[2], a1[3], bb1[0], bb1[1]);
                mma16816(acc[1][3], a1[0], a1[1], a1[2], a1[3], bb1[2], bb1[3]);
            }
            if (it + 5 < NIT) {
                const int wslot = (it + 5) % PSTAGES;   // const-folded
                ISSUE(wslot, (it + 5) * KT, hbuf);
            } else {
                CP_COMMIT();
            }
        }

        {
            __half* gs = gsum + (size_t)(g * 2 + wk) * GSLAB;
            #pragma unroll
            for (int mf = 0; mf < 2; ++mf) {
                const int row = wm * 32 + mf * 16 + gq;
                #pragma unroll
                for (int nf = 0; nf < 4; ++nf) {
                    const int col = wn * 32 + nf * 8 + tq * 2;
                    *(__half2*)&gs[row * GSTR + col] =
                        __floats2half2_rn(acc[mf][nf][0], acc[mf][nf][1]);
                    *(__half2*)&gs[(row + 8) * GSTR + col] =
                        __floats2half2_rn(acc[mf][nf][2], acc[mf][nf][3]);
                }
            }
        }
        __syncthreads();

        __half* hN = d_h16[(t + 1) & 1];
        float e1, e2;
        {
            const __half* gb = gsum + (size_t)b1 * GSTR;
            float ip = __half2float(gb[jj1]) + __half2float(gb[GSLAB + jj1])
                     + __half2float(gb[2*GSLAB + jj1]) + __half2float(gb[3*GSLAB + jj1]) + xv1[0];
            float fpv= __half2float(gb[16+jj1]) + __half2float(gb[GSLAB+16+jj1])
                     + __half2float(gb[2*GSLAB+16+jj1]) + __half2float(gb[3*GSLAB+16+jj1]) + xv1[1];
            float gp = __half2float(gb[32+jj1]) + __half2float(gb[GSLAB+32+jj1])
                     + __half2float(gb[2*GSLAB+32+jj1]) + __half2float(gb[3*GSLAB+32+jj1]) + xv1[2];
            float op = __half2float(gb[48+jj1]) + __half2float(gb[GSLAB+48+jj1])
                     + __half2float(gb[2*GSLAB+48+jj1]) + __half2float(gb[3*GSLAB+48+jj1]) + xv1[3];
            float ii = sigmoid_hw(ip), ff = sigmoid_hw(fpv);
            float gg = tanh_hw(gp),    oo = sigmoid_hw(op);
            float cn = ff * creg1 + ii * gg;
            creg1 = cn;
            float hn = oo * tanh_hw(cn);
            hN[b1 * HDIM + cta * 16 + jj1] = __float2half(hn);
            if (t == T_STEPS - 1) {
                out[HOFF + (size_t)b1 * HDIM + cta * 16 + jj1] = hn;
                out[COFF + (size_t)b1 * HDIM + cta * 16 + jj1] = cn;
            }
            e1 = exp_hw(hn);
        }
        {
            const __half* gb = gsum + (size_t)b2 * GSTR;
            float ip = __half2float(gb[jj2]) + __half2float(gb[GSLAB + jj2])
                     + __half2float(gb[2*GSLAB + jj2]) + __half2float(gb[3*GSLAB + jj2]) + xv2[0];
            float fpv= __half2float(gb[16+jj2]) + __half2float(gb[GSLAB+16+jj2])
                     + __half2float(gb[2*GSLAB+16+jj2]) + __half2float(gb[3*GSLAB+16+jj2]) + xv2[1];
            float gp = __half2float(gb[32+jj2]) + __half2float(gb[GSLAB+32+jj2])
                     + __half2float(gb[2*GSLAB+32+jj2]) + __half2float(gb[3*GSLAB+32+jj2]) + xv2[2];
            float op = __half2float(gb[48+jj2]) + __half2float(gb[GSLAB+48+jj2])
                     + __half2float(gb[2*GSLAB+48+jj2]) + __half2float(gb[3*GSLAB+48+jj2]) + xv2[3];
            float ii = sigmoid_hw(ip), ff = sigmoid_hw(fpv);
            float gg = tanh_hw(gp),    oo = sigmoid_hw(op);
            float cn = ff * creg2 + ii * gg;
            creg2 = cn;
            float hn = oo * tanh_hw(cn);
            hN[b2 * HDIM + cta * 16 + jj2] = __float2half(hn);
            if (t == T_STEPS - 1) {
                out[HOFF + (size_t)b2 * HDIM + cta * 16 + jj2] = hn;
                out[COFF + (size_t)b2 * HDIM + cta * 16 + jj2] = cn;
            }
            e2 = exp_hw(hn);
        }
        float v1 = e1, v2 = e2;
        #pragma unroll
        for (int o = 8; o > 0; o >>= 1) {
            v1 += __shfl_xor_sync(0xffffffffu, v1, o);
            v2 += __shfl_xor_sync(0xffffffffu, v2, o);
        }

        bar_target += NCTAS;
        grid_barrier(bar_target);

        if (t + 1 < T_STEPS) {
            const __half* hnext = d_h16[(t + 1) & 1];
            #pragma unroll
            for (int st = 0; st < 5; ++st) ISSUE(st, st * KT, hnext);
        }
        if (t > 0) {
            float s1 = __ldcg(&d_sum[(t - 1) * BATCH + b1]);
            float s2 = __ldcg(&d_sum[(t - 1) * BATCH + b2]);
            out[(size_t)(t - 1) * BATCH * HDIM + (size_t)b1 * HDIM + cta * 16 + jj1] = pe1 * (1.0f / s1);
            out[(size_t)(t - 1) * BATCH * HDIM + (size_t)b2 * HDIM + cta * 16 + jj2] = pe2 * (1.0f / s2);
        }
        if ((lane & 15) == 0) {
            atomicAdd(&d_sum[t * BATCH + b1], v1);
            atomicAdd(&d_sum[t * BATCH + b2], v2);
        }
        pe1 = e1;
        pe2 = e2;
    }

    bar_target += NCTAS;
    grid_barrier(bar_target);
    {
        float s1 = __ldcg(&d_sum[(T_STEPS - 1) * BATCH + b1]);
        float s2 = __ldcg(&d_sum[(T_STEPS - 1) * BATCH + b2]);
        out[(size_t)(T_STEPS - 1) * BATCH * HDIM + (size_t)b1 * HDIM + cta * 16 + jj1] = pe1 * (1.0f / s1);
        out[(size_t)(T_STEPS - 1) * BATCH * HDIM + (size_t)b2 * HDIM + cta * 16 + jj2] = pe2 * (1.0f / s2);
    }
#undef ISSUE
}

// ---------------- entry ----------------
extern "C" void kernel_launch(void* const* d_in, const int* in_sizes, int n_in,
                              void* d_out, int out_size)
{
    (void)in_sizes; (void)n_in; (void)out_size;
    const float* input = (const float*)d_in[0];
    const float* h0    = (const float*)d_in[1];
    const float* c0    = (const float*)d_in[2];
    const float* wih   = (const float*)d_in[3];
    const float* whh   = (const float*)d_in[4];
    const float* bih   = (const float*)d_in[5];
    const float* bhh   = (const float*)d_in[6];

    cudaFuncSetAttribute(xproj_kernel,
                         cudaFuncAttributeMaxDynamicSharedMemorySize, X2SMEM);
    cudaFuncSetAttribute(lstm_persistent_c0,
                         cudaFuncAttributeMaxDynamicSharedMemorySize, PSMEM);

    prep_kernel<<<1024, 256>>>(input, h0, c0, wih, whh, bih, bhh);
    xproj_kernel<<<dim3(G4 / 128, (T_STEPS * BATCH) / 128), X2THREADS, X2SMEM>>>();
    lstm_persistent_c0<<<NCTAS, PTHREADS, PSMEM>>>((float*)d_out, c0);
}